// round 5
// baseline (speedup 1.0000x reference)
#include <cuda_runtime.h>
#include <cuda_fp16.h>
#include <math.h>
#include <stdint.h>

#define MAXE 400000
#define MAXN 50000
#define ZP   2112   // z row pitch in halves: 64*32 (l,o) + 32 bias + 32 pad

// Scratch (device globals: the sanctioned alloc-free workaround)
__device__ __half g_e2h[(size_t)MAXE * 64];   // 51 MB: edge MLP output (fp16)
__device__ __half g_Btz[(size_t)ZP * 32];     // [j][h]: Wm2 reshaped+transposed (+bias cols)
__device__ __half g_z[(size_t)MAXN * ZP];     // 211 MB: per-node z = h @ Wm2r (+ bias)
__device__ float  g_h0[(size_t)MAXN * 32];
__device__ float  g_ha[(size_t)MAXN * 32];
__device__ float  g_hb[(size_t)MAXN * 32];
__device__ float  g_agg[(size_t)MAXN * 32];

// ---------------------------------------------------------------------------
// init: h0 = [x, zeros], agg = 0
// ---------------------------------------------------------------------------
__global__ void k_init(const float* __restrict__ x, int N) {
    int i = blockIdx.x * blockDim.x + threadIdx.x;
    if (i < N * 32) {
        int n = i >> 5, o = i & 31;
        g_h0[i] = (o < 16) ? x[n * 16 + o] : 0.0f;
        g_agg[i] = 0.0f;
    }
}

// ---------------------------------------------------------------------------
// convBtz: g_Btz[j][h], j = l*32+o (j<2048) -> Wm2[l][h*32+o];
//          j in [2048,2080) -> bm2[h*32+(j-2048)]; j >= 2080 -> 0
// ---------------------------------------------------------------------------
__global__ void k_convBtz(const float* __restrict__ Wm2, const float* __restrict__ bm2) {
    int i = blockIdx.x * blockDim.x + threadIdx.x;
    if (i >= ZP * 32) return;
    int j = i >> 5, h = i & 31;
    float v = 0.f;
    if (j < 2048) {
        int l = j >> 5, o = j & 31;
        v = Wm2[l * 1024 + h * 32 + o];
    } else if (j < 2080) {
        v = bm2[h * 32 + (j - 2048)];
    }
    g_Btz[(size_t)j * 32 + h] = __float2half_rn(v);
}

// ---------------------------------------------------------------------------
// edge MLP: e2 = relu(relu(ea@Wm0+bm0)@Wm1+bm1)  (fp32 math, fp16 output)
// ---------------------------------------------------------------------------
__global__ __launch_bounds__(128) void k_edge_mlp(
    const float* __restrict__ ea,
    const float* __restrict__ Wm0, const float* __restrict__ bm0,
    const float* __restrict__ Wm1, const float* __restrict__ bm1, int E) {
    __shared__ float sW0[16 * 64];
    __shared__ float sW1[64 * 64];
    __shared__ float sb0[64], sb1[64];
    int tid = threadIdx.x;
    for (int i = tid; i < 16 * 64; i += 128) sW0[i] = Wm0[i];
    for (int i = tid; i < 64 * 64; i += 128) sW1[i] = Wm1[i];
    if (tid < 64) { sb0[tid] = bm0[tid]; sb1[tid] = bm1[tid]; }
    __syncthreads();

    int e = blockIdx.x * 128 + tid;
    if (e >= E) return;

    float a[16];
#pragma unroll
    for (int k4 = 0; k4 < 4; k4++) {
        float4 v = *(const float4*)(ea + (size_t)e * 16 + k4 * 4);
        a[k4 * 4 + 0] = v.x; a[k4 * 4 + 1] = v.y;
        a[k4 * 4 + 2] = v.z; a[k4 * 4 + 3] = v.w;
    }

    float h1[64];
#pragma unroll
    for (int l4 = 0; l4 < 16; l4++) {
        float s0 = sb0[l4 * 4 + 0], s1 = sb0[l4 * 4 + 1];
        float s2 = sb0[l4 * 4 + 2], s3 = sb0[l4 * 4 + 3];
#pragma unroll
        for (int k = 0; k < 16; k++) {
            float4 w = *(const float4*)&sW0[k * 64 + l4 * 4];
            float av = a[k];
            s0 += av * w.x; s1 += av * w.y; s2 += av * w.z; s3 += av * w.w;
        }
        h1[l4 * 4 + 0] = fmaxf(s0, 0.f); h1[l4 * 4 + 1] = fmaxf(s1, 0.f);
        h1[l4 * 4 + 2] = fmaxf(s2, 0.f); h1[l4 * 4 + 3] = fmaxf(s3, 0.f);
    }

    __half* outp = g_e2h + (size_t)e * 64;
#pragma unroll
    for (int j4 = 0; j4 < 16; j4++) {
        float s0 = sb1[j4 * 4 + 0], s1 = sb1[j4 * 4 + 1];
        float s2 = sb1[j4 * 4 + 2], s3 = sb1[j4 * 4 + 3];
#pragma unroll
        for (int l = 0; l < 64; l++) {
            float4 w = *(const float4*)&sW1[l * 64 + j4 * 4];
            float hv = h1[l];
            s0 += hv * w.x; s1 += hv * w.y; s2 += hv * w.z; s3 += hv * w.w;
        }
        __half2 p0 = __floats2half2_rn(fmaxf(s0, 0.f), fmaxf(s1, 0.f));
        __half2 p1 = __floats2half2_rn(fmaxf(s2, 0.f), fmaxf(s3, 0.f));
        uint2 pk;
        pk.x = *(unsigned*)&p0; pk.y = *(unsigned*)&p1;
        *(uint2*)(outp + j4 * 4) = pk;
    }
}

// ---------------------------------------------------------------------------
// z GEMM (fp16 tensor cores): g_z[N, 2080] = h[N,32] @ g_Btz^T  (K=32)
// block 128M x 64N, 8 warps (4M x 2N, warp tile 32x32), mma.m16n8k16
// ---------------------------------------------------------------------------
#define ZAP 40   // sA pitch (halves)
#define ZBP 40   // sB pitch (halves)

__global__ __launch_bounds__(256) void k_zgemm(int selIn, int N) {
    __shared__ __half sA[128 * ZAP];   // [row][k=0..31]
    __shared__ __half sB[64 * ZBP];    // [n][k=0..31]

    const float* __restrict__ h = (selIn == 0) ? g_h0 : (selIn == 1) ? g_ha : g_hb;
    int bm = blockIdx.x * 128;
    int bn = blockIdx.y * 64;
    int tid = threadIdx.x;

    // stage A: 128 rows x 32 fp32 -> fp16
    {
        int r = tid >> 1;              // 0..127
        int part = (tid & 1) * 16;     // 0 or 16
        int rr = bm + r; if (rr >= N) rr = N - 1;
        const float4* src = (const float4*)(h + (size_t)rr * 32 + part);
        float4 v0 = src[0], v1 = src[1], v2 = src[2], v3 = src[3];
        __half* dst = sA + r * ZAP + part;
        __half2 p;
        p = __floats2half2_rn(v0.x, v0.y); *(__half2*)(dst + 0)  = p;
        p = __floats2half2_rn(v0.z, v0.w); *(__half2*)(dst + 2)  = p;
        p = __floats2half2_rn(v1.x, v1.y); *(__half2*)(dst + 4)  = p;
        p = __floats2half2_rn(v1.z, v1.w); *(__half2*)(dst + 6)  = p;
        p = __floats2half2_rn(v2.x, v2.y); *(__half2*)(dst + 8)  = p;
        p = __floats2half2_rn(v2.z, v2.w); *(__half2*)(dst + 10) = p;
        p = __floats2half2_rn(v3.x, v3.y); *(__half2*)(dst + 12) = p;
        p = __floats2half2_rn(v3.z, v3.w); *(__half2*)(dst + 14) = p;
    }
    // stage B: 64 rows (cols of z) x 32 halves from g_Btz
    {
        int n = tid >> 2;      // 0..63
        int x = tid & 3;       // uint4 idx
        uint4 v = *(const uint4*)(g_Btz + (size_t)(bn + n) * 32 + x * 8);
        *(uint4*)((char*)(sB + n * ZBP) + x * 16) = v;
    }
    __syncthreads();

    int lane = tid & 31;
    int warp = tid >> 5;
    int wm = warp & 3;    // M strip of 32
    int wn = warp >> 2;   // N strip of 32
    int g = lane >> 2;
    int c = lane & 3;

    float acc[2][4][4];
#pragma unroll
    for (int mt = 0; mt < 2; mt++)
#pragma unroll
        for (int nt = 0; nt < 4; nt++)
#pragma unroll
            for (int q = 0; q < 4; q++) acc[mt][nt][q] = 0.f;

#pragma unroll
    for (int kk = 0; kk < 2; kk++) {
        int kb = kk * 16;
        unsigned a_[2][4];
#pragma unroll
        for (int mt = 0; mt < 2; mt++) {
            int r0 = wm * 32 + mt * 16 + g;
            a_[mt][0] = *(const unsigned*)&sA[r0 * ZAP + kb + 2 * c];
            a_[mt][1] = *(const unsigned*)&sA[(r0 + 8) * ZAP + kb + 2 * c];
            a_[mt][2] = *(const unsigned*)&sA[r0 * ZAP + kb + 2 * c + 8];
            a_[mt][3] = *(const unsigned*)&sA[(r0 + 8) * ZAP + kb + 2 * c + 8];
        }
        unsigned b_[4][2];
#pragma unroll
        for (int nt = 0; nt < 4; nt++) {
            int n0 = wn * 32 + nt * 8 + g;
            b_[nt][0] = *(const unsigned*)&sB[n0 * ZBP + kb + 2 * c];
            b_[nt][1] = *(const unsigned*)&sB[n0 * ZBP + kb + 2 * c + 8];
        }
#pragma unroll
        for (int mt = 0; mt < 2; mt++)
#pragma unroll
            for (int nt = 0; nt < 4; nt++) {
                asm volatile(
                    "mma.sync.aligned.m16n8k16.row.col.f32.f16.f16.f32 "
                    "{%0,%1,%2,%3}, {%4,%5,%6,%7}, {%8,%9}, {%0,%1,%2,%3};"
                    : "+f"(acc[mt][nt][0]), "+f"(acc[mt][nt][1]),
                      "+f"(acc[mt][nt][2]), "+f"(acc[mt][nt][3])
                    : "r"(a_[mt][0]), "r"(a_[mt][1]), "r"(a_[mt][2]), "r"(a_[mt][3]),
                      "r"(b_[nt][0]), "r"(b_[nt][1]));
            }
    }

    // epilogue: write fp16 z (pitch ZP; cols >= 2080 land in padding, harmless)
#pragma unroll
    for (int nt = 0; nt < 4; nt++) {
        int col = bn + wn * 32 + nt * 8 + 2 * c;
#pragma unroll
        for (int mt = 0; mt < 2; mt++) {
            int row0 = bm + wm * 32 + mt * 16 + g;
            if (row0 < N) {
                __half2 v = __floats2half2_rn(acc[mt][nt][0], acc[mt][nt][1]);
                *(__half2*)(g_z + (size_t)row0 * ZP + col) = v;
            }
            int row1 = row0 + 8;
            if (row1 < N) {
                __half2 v = __floats2half2_rn(acc[mt][nt][2], acc[mt][nt][3]);
                *(__half2*)(g_z + (size_t)row1 * ZP + col) = v;
            }
        }
    }
}

// ---------------------------------------------------------------------------
// message passing via z: agg[dst] += e2[e] . z[src]  (one warp per edge)
// chunk c = lane + 32*i covers z halves [8c, 8c+8): l = c/4, o = (c%4)*8..+8
// ---------------------------------------------------------------------------
__global__ __launch_bounds__(256) void k_msgz(const int* __restrict__ ei, int E) {
    int gw = (blockIdx.x * blockDim.x + threadIdx.x) >> 5;
    int lane = threadIdx.x & 31;
    if (gw >= E) return;

    int2 sd = ((const int2*)ei)[gw];
    int src = sd.x, dst = sd.y;

    // e2 pair for halves (2*lane, 2*lane+1)
    __half2 e2p = *(const __half2*)(g_e2h + (size_t)gw * 64 + 2 * lane);
    float2 e2f = __half22float2(e2p);

    const uint4* __restrict__ Z16 = (const uint4*)(g_z + (size_t)src * ZP);
    float acc[8];
#pragma unroll
    for (int j = 0; j < 8; j++) acc[j] = 0.f;

#pragma unroll
    for (int i = 0; i < 8; i++) {
        uint4 w = Z16[lane + 32 * i];
        int l = (lane >> 2) + 8 * i;        // 0..63
        // e2[l]: lane l>>1 holds pair (2*(l>>1), 2*(l>>1)+1); pick by l&1
        float lo = __shfl_sync(0xffffffffu, e2f.x, l >> 1);
        float hi = __shfl_sync(0xffffffffu, e2f.y, l >> 1);
        float hs = (l & 1) ? hi : lo;
        const __half2* h2 = (const __half2*)&w;
#pragma unroll
        for (int j = 0; j < 4; j++) {
            float2 f = __half22float2(h2[j]);
            acc[2 * j]     += hs * f.x;
            acc[2 * j + 1] += hs * f.y;
        }
    }
#pragma unroll
    for (int m = 4; m <= 16; m <<= 1) {
#pragma unroll
        for (int j = 0; j < 8; j++)
            acc[j] += __shfl_xor_sync(0xffffffffu, acc[j], m);
    }
    int k = lane >> 2;
    float v = acc[0];
    if (k == 1) v = acc[1];
    if (k == 2) v = acc[2];
    if (k == 3) v = acc[3];
    if (k == 4) v = acc[4];
    if (k == 5) v = acc[5];
    if (k == 6) v = acc[6];
    if (k == 7) v = acc[7];
    int o = ((lane & 3) << 3) + k;
    v += __half2float(g_z[(size_t)src * ZP + 2048 + o]);   // bias term zb[src][o]
    atomicAdd(&g_agg[(size_t)dst * 32 + o], v);
}

// ---------------------------------------------------------------------------
// node update: h_out = h_in @ root + bias + agg ; agg = 0   (warp per node)
// ---------------------------------------------------------------------------
__global__ __launch_bounds__(256) void k_update(
    int selIn, int selOut, const float* __restrict__ root,
    const float* __restrict__ bias, int N) {
    __shared__ float sroot[32 * 32];
    __shared__ float sb[32];
    int tid = threadIdx.x;
    for (int i = tid; i < 1024; i += 256) sroot[i] = root[i];
    if (tid < 32) sb[tid] = bias[tid];
    __syncthreads();

    int lane = tid & 31, w = tid >> 5;
    int n = blockIdx.x * 8 + w;
    if (n >= N) return;
    const float* __restrict__ hin = (selIn == 0) ? g_h0 : (selIn == 1) ? g_ha : g_hb;
    float* __restrict__ hout = (selOut == 1) ? g_ha : g_hb;

    float hv = hin[(size_t)n * 32 + lane];
    float acc = sb[lane] + g_agg[(size_t)n * 32 + lane];
    g_agg[(size_t)n * 32 + lane] = 0.0f;
#pragma unroll
    for (int k = 0; k < 32; k++)
        acc += __shfl_sync(0xffffffffu, hv, k) * sroot[k * 32 + lane];
    hout[(size_t)n * 32 + lane] = acc;
}

__global__ void k_zero(float* o, int n) {
    int i = blockIdx.x * blockDim.x + threadIdx.x;
    if (i < n) o[i] = 0.0f;
}

// ---------------------------------------------------------------------------
// readout: out = sum_n sigmoid(relu([h,h0]@Wi0+bi0)@Wi1+bi1) *
//                       (relu(h@Wj0+bj0)@Wj1+bj1)
// ---------------------------------------------------------------------------
__global__ __launch_bounds__(256) void k_readout(
    const float* __restrict__ Wi0, const float* __restrict__ bi0,
    const float* __restrict__ Wi1, const float* __restrict__ bi1,
    const float* __restrict__ Wj0, const float* __restrict__ bj0,
    const float* __restrict__ Wj1, const float* __restrict__ bj1,
    float* __restrict__ out, int N) {
    __shared__ float sW[64 * 128];
    __shared__ float sv1[128];
    __shared__ float sblock;
    int tid = threadIdx.x, lane = tid & 31, w = tid >> 5;
    int n = blockIdx.x * 8 + w;
    bool active = (n < N);

    for (int i = tid; i < 64 * 128; i += 256) sW[i] = Wi0[i];
    for (int i = tid; i < 128; i += 256) sv1[i] = Wi1[i];
    if (tid == 0) sblock = 0.f;
    __syncthreads();

    float za = 0.f, zb = 0.f;
    if (active) {
        za = g_ha[(size_t)n * 32 + lane];   // final h
        zb = g_h0[(size_t)n * 32 + lane];   // h0
    }

    float a0 = bi0[lane], a1 = bi0[lane + 32], a2 = bi0[lane + 64], a3 = bi0[lane + 96];
#pragma unroll
    for (int k = 0; k < 32; k++) {
        float zk = __shfl_sync(0xffffffffu, za, k);
        a0 += zk * sW[k * 128 + lane];
        a1 += zk * sW[k * 128 + lane + 32];
        a2 += zk * sW[k * 128 + lane + 64];
        a3 += zk * sW[k * 128 + lane + 96];
    }
#pragma unroll
    for (int k = 0; k < 32; k++) {
        float zk = __shfl_sync(0xffffffffu, zb, k);
        a0 += zk * sW[(k + 32) * 128 + lane];
        a1 += zk * sW[(k + 32) * 128 + lane + 32];
        a2 += zk * sW[(k + 32) * 128 + lane + 64];
        a3 += zk * sW[(k + 32) * 128 + lane + 96];
    }
    a0 = fmaxf(a0, 0.f); a1 = fmaxf(a1, 0.f); a2 = fmaxf(a2, 0.f); a3 = fmaxf(a3, 0.f);
    float gp = a0 * sv1[lane] + a1 * sv1[lane + 32] + a2 * sv1[lane + 64] + a3 * sv1[lane + 96];
#pragma unroll
    for (int s = 16; s > 0; s >>= 1) gp += __shfl_xor_sync(0xffffffffu, gp, s);
    float gate = 1.0f / (1.0f + expf(-(gp + bi1[0])));

    __syncthreads();   // done reading Wi0
    for (int i = tid; i < 32 * 128; i += 256) sW[i] = Wj0[i];
    for (int i = tid; i < 128; i += 256) sv1[i] = Wj1[i];
    __syncthreads();

    float b0 = bj0[lane], b1 = bj0[lane + 32], b2 = bj0[lane + 64], b3 = bj0[lane + 96];
#pragma unroll
    for (int k = 0; k < 32; k++) {
        float zk = __shfl_sync(0xffffffffu, za, k);
        b0 += zk * sW[k * 128 + lane];
        b1 += zk * sW[k * 128 + lane + 32];
        b2 += zk * sW[k * 128 + lane + 64];
        b3 += zk * sW[k * 128 + lane + 96];
    }
    b0 = fmaxf(b0, 0.f); b1 = fmaxf(b1, 0.f); b2 = fmaxf(b2, 0.f); b3 = fmaxf(b3, 0.f);
    float vp = b0 * sv1[lane] + b1 * sv1[lane + 32] + b2 * sv1[lane + 64] + b3 * sv1[lane + 96];
#pragma unroll
    for (int s = 16; s > 0; s >>= 1) vp += __shfl_xor_sync(0xffffffffu, vp, s);
    float val = vp + bj1[0];

    if (active && lane == 0) atomicAdd(&sblock, gate * val);
    __syncthreads();
    if (tid == 0) atomicAdd(out, sblock);
}

// ---------------------------------------------------------------------------
extern "C" void kernel_launch(void* const* d_in, const int* in_sizes, int n_in,
                              void* d_out, int out_size) {
    const float* x   = (const float*)d_in[0];
    const int*   ei  = (const int*)d_in[1];
    const float* ea  = (const float*)d_in[2];
    const float* Wm0 = (const float*)d_in[3];  const float* bm0 = (const float*)d_in[4];
    const float* Wm1 = (const float*)d_in[5];  const float* bm1 = (const float*)d_in[6];
    const float* Wm2 = (const float*)d_in[7];  const float* bm2 = (const float*)d_in[8];
    const float* root= (const float*)d_in[9];  const float* bias= (const float*)d_in[10];
    const float* Wi0 = (const float*)d_in[11]; const float* bi0 = (const float*)d_in[12];
    const float* Wi1 = (const float*)d_in[13]; const float* bi1 = (const float*)d_in[14];
    const float* Wj0 = (const float*)d_in[15]; const float* bj0 = (const float*)d_in[16];
    const float* Wj1 = (const float*)d_in[17]; const float* bj1 = (const float*)d_in[18];
    int N = in_sizes[0] / 16;
    int E = in_sizes[2] / 16;
    float* out = (float*)d_out;

    k_init<<<(N * 32 + 255) / 256, 256>>>(x, N);
    k_convBtz<<<(ZP * 32 + 255) / 256, 256>>>(Wm2, bm2);
    k_edge_mlp<<<(E + 127) / 128, 128>>>(ea, Wm0, bm0, Wm1, bm1, E);

    dim3 zg((N + 127) / 128, (ZP) / 64);   // 2112/64 = 33 N-blocks
    int msgBlocks = (E + 7) / 8;
    int nodeBlocks = (N + 7) / 8;

    // iter 1: h0 -> ha
    k_zgemm<<<zg, 256>>>(0, N);
    k_msgz<<<msgBlocks, 256>>>(ei, E);
    k_update<<<nodeBlocks, 256>>>(0, 1, root, bias, N);
    // iter 2: ha -> hb
    k_zgemm<<<zg, 256>>>(1, N);
    k_msgz<<<msgBlocks, 256>>>(ei, E);
    k_update<<<nodeBlocks, 256>>>(1, 2, root, bias, N);
    // iter 3: hb -> ha
    k_zgemm<<<zg, 256>>>(2, N);
    k_msgz<<<msgBlocks, 256>>>(ei, E);
    k_update<<<nodeBlocks, 256>>>(2, 1, root, bias, N);

    k_zero<<<1, 32>>>(out, out_size);
    k_readout<<<nodeBlocks, 256>>>(Wi0, bi0, Wi1, bi1, Wj0, bj0, Wj1, bj1, out, N);
}

// round 6
// speedup vs baseline: 1.0014x; 1.0014x over previous
#include <cuda_runtime.h>
#include <cuda_fp16.h>
#include <math.h>
#include <stdint.h>

#define MAXE 400000
#define MAXN 50000
#define ZP   2112   // z row pitch in halves: 64*32 (l,o) + 32 bias + 32 pad

// Scratch (device globals: the sanctioned alloc-free workaround)
__device__ __half g_e2h[(size_t)MAXE * 64];   // 51 MB: edge MLP output (fp16)
__device__ __half g_Btz[(size_t)ZP * 32];     // [j][h]: Wm2 reshaped+transposed (+bias cols)
__device__ __half g_z[(size_t)MAXN * ZP];     // 211 MB: per-node z = h @ Wm2r (+ bias)
__device__ float  g_h0[(size_t)MAXN * 32];
__device__ float  g_ha[(size_t)MAXN * 32];
__device__ float  g_hb[(size_t)MAXN * 32];
__device__ float  g_agg[(size_t)MAXN * 32];

// ---------------------------------------------------------------------------
// init: h0 = [x, zeros], agg = 0
// ---------------------------------------------------------------------------
__global__ void k_init(const float* __restrict__ x, int N) {
    int i = blockIdx.x * blockDim.x + threadIdx.x;
    if (i < N * 32) {
        int n = i >> 5, o = i & 31;
        g_h0[i] = (o < 16) ? x[n * 16 + o] : 0.0f;
        g_agg[i] = 0.0f;
    }
}

// ---------------------------------------------------------------------------
// convBtz: g_Btz[j][h], j = l*32+o (j<2048) -> Wm2[l][h*32+o];
//          j in [2048,2080) -> bm2[h*32+(j-2048)]; j >= 2080 -> 0
// ---------------------------------------------------------------------------
__global__ void k_convBtz(const float* __restrict__ Wm2, const float* __restrict__ bm2) {
    int i = blockIdx.x * blockDim.x + threadIdx.x;
    if (i >= ZP * 32) return;
    int j = i >> 5, h = i & 31;
    float v = 0.f;
    if (j < 2048) {
        int l = j >> 5, o = j & 31;
        v = Wm2[l * 1024 + h * 32 + o];
    } else if (j < 2080) {
        v = bm2[h * 32 + (j - 2048)];
    }
    g_Btz[(size_t)j * 32 + h] = __float2half_rn(v);
}

// ---------------------------------------------------------------------------
// edge MLP: e2 = relu(relu(ea@Wm0+bm0)@Wm1+bm1)  (fp32 math, fp16 output)
// ---------------------------------------------------------------------------
__global__ __launch_bounds__(128) void k_edge_mlp(
    const float* __restrict__ ea,
    const float* __restrict__ Wm0, const float* __restrict__ bm0,
    const float* __restrict__ Wm1, const float* __restrict__ bm1, int E) {
    __shared__ float sW0[16 * 64];
    __shared__ float sW1[64 * 64];
    __shared__ float sb0[64], sb1[64];
    int tid = threadIdx.x;
    for (int i = tid; i < 16 * 64; i += 128) sW0[i] = Wm0[i];
    for (int i = tid; i < 64 * 64; i += 128) sW1[i] = Wm1[i];
    if (tid < 64) { sb0[tid] = bm0[tid]; sb1[tid] = bm1[tid]; }
    __syncthreads();

    int e = blockIdx.x * 128 + tid;
    if (e >= E) return;

    float a[16];
#pragma unroll
    for (int k4 = 0; k4 < 4; k4++) {
        float4 v = *(const float4*)(ea + (size_t)e * 16 + k4 * 4);
        a[k4 * 4 + 0] = v.x; a[k4 * 4 + 1] = v.y;
        a[k4 * 4 + 2] = v.z; a[k4 * 4 + 3] = v.w;
    }

    float h1[64];
#pragma unroll
    for (int l4 = 0; l4 < 16; l4++) {
        float s0 = sb0[l4 * 4 + 0], s1 = sb0[l4 * 4 + 1];
        float s2 = sb0[l4 * 4 + 2], s3 = sb0[l4 * 4 + 3];
#pragma unroll
        for (int k = 0; k < 16; k++) {
            float4 w = *(const float4*)&sW0[k * 64 + l4 * 4];
            float av = a[k];
            s0 += av * w.x; s1 += av * w.y; s2 += av * w.z; s3 += av * w.w;
        }
        h1[l4 * 4 + 0] = fmaxf(s0, 0.f); h1[l4 * 4 + 1] = fmaxf(s1, 0.f);
        h1[l4 * 4 + 2] = fmaxf(s2, 0.f); h1[l4 * 4 + 3] = fmaxf(s3, 0.f);
    }

    __half* outp = g_e2h + (size_t)e * 64;
#pragma unroll
    for (int j4 = 0; j4 < 16; j4++) {
        float s0 = sb1[j4 * 4 + 0], s1 = sb1[j4 * 4 + 1];
        float s2 = sb1[j4 * 4 + 2], s3 = sb1[j4 * 4 + 3];
#pragma unroll
        for (int l = 0; l < 64; l++) {
            float4 w = *(const float4*)&sW1[l * 64 + j4 * 4];
            float hv = h1[l];
            s0 += hv * w.x; s1 += hv * w.y; s2 += hv * w.z; s3 += hv * w.w;
        }
        __half2 p0 = __floats2half2_rn(fmaxf(s0, 0.f), fmaxf(s1, 0.f));
        __half2 p1 = __floats2half2_rn(fmaxf(s2, 0.f), fmaxf(s3, 0.f));
        uint2 pk;
        pk.x = *(unsigned*)&p0; pk.y = *(unsigned*)&p1;
        *(uint2*)(outp + j4 * 4) = pk;
    }
}

// ---------------------------------------------------------------------------
// z GEMM (fp16 tensor cores): g_z[N, 2080] = h[N,32] @ g_Btz^T  (K=32)
// block 128M x 64N, 8 warps (4M x 2N, warp tile 32x32), mma.m16n8k16
// ---------------------------------------------------------------------------
#define ZAP 40   // sA pitch (halves)
#define ZBP 40   // sB pitch (halves)

__global__ __launch_bounds__(256) void k_zgemm(int selIn, int N) {
    __shared__ __half sA[128 * ZAP];   // [row][k=0..31]
    __shared__ __half sB[64 * ZBP];    // [n][k=0..31]

    const float* __restrict__ h = (selIn == 0) ? g_h0 : (selIn == 1) ? g_ha : g_hb;
    int bm = blockIdx.x * 128;
    int bn = blockIdx.y * 64;
    int tid = threadIdx.x;

    // stage A: 128 rows x 32 fp32 -> fp16
    {
        int r = tid >> 1;              // 0..127
        int part = (tid & 1) * 16;     // 0 or 16
        int rr = bm + r; if (rr >= N) rr = N - 1;
        const float4* src = (const float4*)(h + (size_t)rr * 32 + part);
        float4 v0 = src[0], v1 = src[1], v2 = src[2], v3 = src[3];
        __half* dst = sA + r * ZAP + part;
        __half2 p;
        p = __floats2half2_rn(v0.x, v0.y); *(__half2*)(dst + 0)  = p;
        p = __floats2half2_rn(v0.z, v0.w); *(__half2*)(dst + 2)  = p;
        p = __floats2half2_rn(v1.x, v1.y); *(__half2*)(dst + 4)  = p;
        p = __floats2half2_rn(v1.z, v1.w); *(__half2*)(dst + 6)  = p;
        p = __floats2half2_rn(v2.x, v2.y); *(__half2*)(dst + 8)  = p;
        p = __floats2half2_rn(v2.z, v2.w); *(__half2*)(dst + 10) = p;
        p = __floats2half2_rn(v3.x, v3.y); *(__half2*)(dst + 12) = p;
        p = __floats2half2_rn(v3.z, v3.w); *(__half2*)(dst + 14) = p;
    }
    // stage B: 64 rows (cols of z) x 32 halves from g_Btz
    {
        int n = tid >> 2;      // 0..63
        int x = tid & 3;       // uint4 idx
        uint4 v = *(const uint4*)(g_Btz + (size_t)(bn + n) * 32 + x * 8);
        *(uint4*)((char*)(sB + n * ZBP) + x * 16) = v;
    }
    __syncthreads();

    int lane = tid & 31;
    int warp = tid >> 5;
    int wm = warp & 3;    // M strip of 32
    int wn = warp >> 2;   // N strip of 32
    int g = lane >> 2;
    int c = lane & 3;

    float acc[2][4][4];
#pragma unroll
    for (int mt = 0; mt < 2; mt++)
#pragma unroll
        for (int nt = 0; nt < 4; nt++)
#pragma unroll
            for (int q = 0; q < 4; q++) acc[mt][nt][q] = 0.f;

#pragma unroll
    for (int kk = 0; kk < 2; kk++) {
        int kb = kk * 16;
        unsigned a_[2][4];
#pragma unroll
        for (int mt = 0; mt < 2; mt++) {
            int r0 = wm * 32 + mt * 16 + g;
            a_[mt][0] = *(const unsigned*)&sA[r0 * ZAP + kb + 2 * c];
            a_[mt][1] = *(const unsigned*)&sA[(r0 + 8) * ZAP + kb + 2 * c];
            a_[mt][2] = *(const unsigned*)&sA[r0 * ZAP + kb + 2 * c + 8];
            a_[mt][3] = *(const unsigned*)&sA[(r0 + 8) * ZAP + kb + 2 * c + 8];
        }
        unsigned b_[4][2];
#pragma unroll
        for (int nt = 0; nt < 4; nt++) {
            int n0 = wn * 32 + nt * 8 + g;
            b_[nt][0] = *(const unsigned*)&sB[n0 * ZBP + kb + 2 * c];
            b_[nt][1] = *(const unsigned*)&sB[n0 * ZBP + kb + 2 * c + 8];
        }
#pragma unroll
        for (int mt = 0; mt < 2; mt++)
#pragma unroll
            for (int nt = 0; nt < 4; nt++) {
                asm volatile(
                    "mma.sync.aligned.m16n8k16.row.col.f32.f16.f16.f32 "
                    "{%0,%1,%2,%3}, {%4,%5,%6,%7}, {%8,%9}, {%0,%1,%2,%3};"
                    : "+f"(acc[mt][nt][0]), "+f"(acc[mt][nt][1]),
                      "+f"(acc[mt][nt][2]), "+f"(acc[mt][nt][3])
                    : "r"(a_[mt][0]), "r"(a_[mt][1]), "r"(a_[mt][2]), "r"(a_[mt][3]),
                      "r"(b_[nt][0]), "r"(b_[nt][1]));
            }
    }

    // epilogue: write fp16 z (pitch ZP; cols >= 2080 land in padding, harmless)
#pragma unroll
    for (int nt = 0; nt < 4; nt++) {
        int col = bn + wn * 32 + nt * 8 + 2 * c;
#pragma unroll
        for (int mt = 0; mt < 2; mt++) {
            int row0 = bm + wm * 32 + mt * 16 + g;
            if (row0 < N) {
                __half2 v = __floats2half2_rn(acc[mt][nt][0], acc[mt][nt][1]);
                *(__half2*)(g_z + (size_t)row0 * ZP + col) = v;
            }
            int row1 = row0 + 8;
            if (row1 < N) {
                __half2 v = __floats2half2_rn(acc[mt][nt][2], acc[mt][nt][3]);
                *(__half2*)(g_z + (size_t)row1 * ZP + col) = v;
            }
        }
    }
}

// ---------------------------------------------------------------------------
// message passing via z: agg[dst] += e2[e] . z[src]  (one warp per edge)
// chunk c = lane + 32*i covers z halves [8c, 8c+8): l = c/4, o = (c%4)*8..+8
// ---------------------------------------------------------------------------
__global__ __launch_bounds__(256) void k_msgz(const int* __restrict__ ei, int E) {
    int gw = (blockIdx.x * blockDim.x + threadIdx.x) >> 5;
    int lane = threadIdx.x & 31;
    if (gw >= E) return;

    int2 sd = ((const int2*)ei)[gw];
    int src = sd.x, dst = sd.y;

    // e2 pair for halves (2*lane, 2*lane+1)
    __half2 e2p = *(const __half2*)(g_e2h + (size_t)gw * 64 + 2 * lane);
    float2 e2f = __half22float2(e2p);

    const uint4* __restrict__ Z16 = (const uint4*)(g_z + (size_t)src * ZP);
    float acc[8];
#pragma unroll
    for (int j = 0; j < 8; j++) acc[j] = 0.f;

#pragma unroll
    for (int i = 0; i < 8; i++) {
        uint4 w = Z16[lane + 32 * i];
        int l = (lane >> 2) + 8 * i;        // 0..63
        // e2[l]: lane l>>1 holds pair (2*(l>>1), 2*(l>>1)+1); pick by l&1
        float lo = __shfl_sync(0xffffffffu, e2f.x, l >> 1);
        float hi = __shfl_sync(0xffffffffu, e2f.y, l >> 1);
        float hs = (l & 1) ? hi : lo;
        const __half2* h2 = (const __half2*)&w;
#pragma unroll
        for (int j = 0; j < 4; j++) {
            float2 f = __half22float2(h2[j]);
            acc[2 * j]     += hs * f.x;
            acc[2 * j + 1] += hs * f.y;
        }
    }
#pragma unroll
    for (int m = 4; m <= 16; m <<= 1) {
#pragma unroll
        for (int j = 0; j < 8; j++)
            acc[j] += __shfl_xor_sync(0xffffffffu, acc[j], m);
    }
    int k = lane >> 2;
    float v = acc[0];
    if (k == 1) v = acc[1];
    if (k == 2) v = acc[2];
    if (k == 3) v = acc[3];
    if (k == 4) v = acc[4];
    if (k == 5) v = acc[5];
    if (k == 6) v = acc[6];
    if (k == 7) v = acc[7];
    int o = ((lane & 3) << 3) + k;
    v += __half2float(g_z[(size_t)src * ZP + 2048 + o]);   // bias term zb[src][o]
    atomicAdd(&g_agg[(size_t)dst * 32 + o], v);
}

// ---------------------------------------------------------------------------
// node update: h_out = h_in @ root + bias + agg ; agg = 0   (warp per node)
// ---------------------------------------------------------------------------
__global__ __launch_bounds__(256) void k_update(
    int selIn, int selOut, const float* __restrict__ root,
    const float* __restrict__ bias, int N) {
    __shared__ float sroot[32 * 32];
    __shared__ float sb[32];
    int tid = threadIdx.x;
    for (int i = tid; i < 1024; i += 256) sroot[i] = root[i];
    if (tid < 32) sb[tid] = bias[tid];
    __syncthreads();

    int lane = tid & 31, w = tid >> 5;
    int n = blockIdx.x * 8 + w;
    if (n >= N) return;
    const float* __restrict__ hin = (selIn == 0) ? g_h0 : (selIn == 1) ? g_ha : g_hb;
    float* __restrict__ hout = (selOut == 1) ? g_ha : g_hb;

    float hv = hin[(size_t)n * 32 + lane];
    float acc = sb[lane] + g_agg[(size_t)n * 32 + lane];
    g_agg[(size_t)n * 32 + lane] = 0.0f;
#pragma unroll
    for (int k = 0; k < 32; k++)
        acc += __shfl_sync(0xffffffffu, hv, k) * sroot[k * 32 + lane];
    hout[(size_t)n * 32 + lane] = acc;
}

__global__ void k_zero(float* o, int n) {
    int i = blockIdx.x * blockDim.x + threadIdx.x;
    if (i < n) o[i] = 0.0f;
}

// ---------------------------------------------------------------------------
// readout: out = sum_n sigmoid(relu([h,h0]@Wi0+bi0)@Wi1+bi1) *
//                       (relu(h@Wj0+bj0)@Wj1+bj1)
// ---------------------------------------------------------------------------
__global__ __launch_bounds__(256) void k_readout(
    const float* __restrict__ Wi0, const float* __restrict__ bi0,
    const float* __restrict__ Wi1, const float* __restrict__ bi1,
    const float* __restrict__ Wj0, const float* __restrict__ bj0,
    const float* __restrict__ Wj1, const float* __restrict__ bj1,
    float* __restrict__ out, int N) {
    __shared__ float sW[64 * 128];
    __shared__ float sv1[128];
    __shared__ float sblock;
    int tid = threadIdx.x, lane = tid & 31, w = tid >> 5;
    int n = blockIdx.x * 8 + w;
    bool active = (n < N);

    for (int i = tid; i < 64 * 128; i += 256) sW[i] = Wi0[i];
    for (int i = tid; i < 128; i += 256) sv1[i] = Wi1[i];
    if (tid == 0) sblock = 0.f;
    __syncthreads();

    float za = 0.f, zb = 0.f;
    if (active) {
        za = g_ha[(size_t)n * 32 + lane];   // final h
        zb = g_h0[(size_t)n * 32 + lane];   // h0
    }

    float a0 = bi0[lane], a1 = bi0[lane + 32], a2 = bi0[lane + 64], a3 = bi0[lane + 96];
#pragma unroll
    for (int k = 0; k < 32; k++) {
        float zk = __shfl_sync(0xffffffffu, za, k);
        a0 += zk * sW[k * 128 + lane];
        a1 += zk * sW[k * 128 + lane + 32];
        a2 += zk * sW[k * 128 + lane + 64];
        a3 += zk * sW[k * 128 + lane + 96];
    }
#pragma unroll
    for (int k = 0; k < 32; k++) {
        float zk = __shfl_sync(0xffffffffu, zb, k);
        a0 += zk * sW[(k + 32) * 128 + lane];
        a1 += zk * sW[(k + 32) * 128 + lane + 32];
        a2 += zk * sW[(k + 32) * 128 + lane + 64];
        a3 += zk * sW[(k + 32) * 128 + lane + 96];
    }
    a0 = fmaxf(a0, 0.f); a1 = fmaxf(a1, 0.f); a2 = fmaxf(a2, 0.f); a3 = fmaxf(a3, 0.f);
    float gp = a0 * sv1[lane] + a1 * sv1[lane + 32] + a2 * sv1[lane + 64] + a3 * sv1[lane + 96];
#pragma unroll
    for (int s = 16; s > 0; s >>= 1) gp += __shfl_xor_sync(0xffffffffu, gp, s);
    float gate = 1.0f / (1.0f + expf(-(gp + bi1[0])));

    __syncthreads();   // done reading Wi0
    for (int i = tid; i < 32 * 128; i += 256) sW[i] = Wj0[i];
    for (int i = tid; i < 128; i += 256) sv1[i] = Wj1[i];
    __syncthreads();

    float b0 = bj0[lane], b1 = bj0[lane + 32], b2 = bj0[lane + 64], b3 = bj0[lane + 96];
#pragma unroll
    for (int k = 0; k < 32; k++) {
        float zk = __shfl_sync(0xffffffffu, za, k);
        b0 += zk * sW[k * 128 + lane];
        b1 += zk * sW[k * 128 + lane + 32];
        b2 += zk * sW[k * 128 + lane + 64];
        b3 += zk * sW[k * 128 + lane + 96];
    }
    b0 = fmaxf(b0, 0.f); b1 = fmaxf(b1, 0.f); b2 = fmaxf(b2, 0.f); b3 = fmaxf(b3, 0.f);
    float vp = b0 * sv1[lane] + b1 * sv1[lane + 32] + b2 * sv1[lane + 64] + b3 * sv1[lane + 96];
#pragma unroll
    for (int s = 16; s > 0; s >>= 1) vp += __shfl_xor_sync(0xffffffffu, vp, s);
    float val = vp + bj1[0];

    if (active && lane == 0) atomicAdd(&sblock, gate * val);
    __syncthreads();
    if (tid == 0) atomicAdd(out, sblock);
}

// ---------------------------------------------------------------------------
extern "C" void kernel_launch(void* const* d_in, const int* in_sizes, int n_in,
                              void* d_out, int out_size) {
    const float* x   = (const float*)d_in[0];
    const int*   ei  = (const int*)d_in[1];
    const float* ea  = (const float*)d_in[2];
    const float* Wm0 = (const float*)d_in[3];  const float* bm0 = (const float*)d_in[4];
    const float* Wm1 = (const float*)d_in[5];  const float* bm1 = (const float*)d_in[6];
    const float* Wm2 = (const float*)d_in[7];  const float* bm2 = (const float*)d_in[8];
    const float* root= (const float*)d_in[9];  const float* bias= (const float*)d_in[10];
    const float* Wi0 = (const float*)d_in[11]; const float* bi0 = (const float*)d_in[12];
    const float* Wi1 = (const float*)d_in[13]; const float* bi1 = (const float*)d_in[14];
    const float* Wj0 = (const float*)d_in[15]; const float* bj0 = (const float*)d_in[16];
    const float* Wj1 = (const float*)d_in[17]; const float* bj1 = (const float*)d_in[18];
    int N = in_sizes[0] / 16;
    int E = in_sizes[2] / 16;
    float* out = (float*)d_out;

    k_init<<<(N * 32 + 255) / 256, 256>>>(x, N);
    k_convBtz<<<(ZP * 32 + 255) / 256, 256>>>(Wm2, bm2);
    k_edge_mlp<<<(E + 127) / 128, 128>>>(ea, Wm0, bm0, Wm1, bm1, E);

    dim3 zg((N + 127) / 128, (ZP) / 64);   // 2112/64 = 33 N-blocks
    int msgBlocks = (E + 7) / 8;
    int nodeBlocks = (N + 7) / 8;

    // iter 1: h0 -> ha
    k_zgemm<<<zg, 256>>>(0, N);
    k_msgz<<<msgBlocks, 256>>>(ei, E);
    k_update<<<nodeBlocks, 256>>>(0, 1, root, bias, N);
    // iter 2: ha -> hb
    k_zgemm<<<zg, 256>>>(1, N);
    k_msgz<<<msgBlocks, 256>>>(ei, E);
    k_update<<<nodeBlocks, 256>>>(1, 2, root, bias, N);
    // iter 3: hb -> ha
    k_zgemm<<<zg, 256>>>(2, N);
    k_msgz<<<msgBlocks, 256>>>(ei, E);
    k_update<<<nodeBlocks, 256>>>(2, 1, root, bias, N);

    k_zero<<<1, 32>>>(out, out_size);
    k_readout<<<nodeBlocks, 256>>>(Wi0, bi0, Wi1, bi1, Wj0, bj0, Wj1, bj1, out, N);
}

// round 7
// speedup vs baseline: 1.2310x; 1.2293x over previous
#include <cuda_runtime.h>
#include <cuda_fp16.h>
#include <math.h>
#include <stdint.h>

#define MAXE 400000
#define MAXN 50000

// Scratch (device globals: the sanctioned alloc-free workaround)
__device__ __half g_e2h[(size_t)MAXE * 64];    // 51 MB: edge MLP output (fp16)
__device__ __half g_Bt[64 * 1024];             // Wm2 transposed [n][k], fp16
__device__ __half g_Wh[(size_t)MAXE * 1024];   // 819 MB: per-edge 32x32 matrices (fp16)
__device__ float  g_h0[(size_t)MAXN * 32];
__device__ float  g_ha[(size_t)MAXN * 32];
__device__ float  g_hb[(size_t)MAXN * 32];
__device__ float  g_agg[(size_t)MAXN * 32];

// ---------------------------------------------------------------------------
// init: h0 = [x, zeros], agg = 0
// ---------------------------------------------------------------------------
__global__ void k_init(const float* __restrict__ x, int N) {
    int i = blockIdx.x * blockDim.x + threadIdx.x;
    if (i < N * 32) {
        int n = i >> 5, o = i & 31;
        g_h0[i] = (o < 16) ? x[n * 16 + o] : 0.0f;
        g_agg[i] = 0.0f;
    }
}

// ---------------------------------------------------------------------------
// convB: g_Bt[n][k] = fp16(Wm2[k][n])   (64x1024 -> 1024x64)
// ---------------------------------------------------------------------------
__global__ void k_convB(const float* __restrict__ B) {
    int i = blockIdx.x * blockDim.x + threadIdx.x;
    if (i < 64 * 1024) {
        int n = i >> 6, k = i & 63;
        g_Bt[i] = __float2half_rn(B[k * 1024 + n]);
    }
}

// ---------------------------------------------------------------------------
// edge MLP: e2 = relu(relu(ea@Wm0+bm0)@Wm1+bm1)  (fp32 math, fp16 output)
// ---------------------------------------------------------------------------
__global__ __launch_bounds__(128) void k_edge_mlp(
    const float* __restrict__ ea,
    const float* __restrict__ Wm0, const float* __restrict__ bm0,
    const float* __restrict__ Wm1, const float* __restrict__ bm1, int E) {
    __shared__ float sW0[16 * 64];
    __shared__ float sW1[64 * 64];
    __shared__ float sb0[64], sb1[64];
    int tid = threadIdx.x;
    for (int i = tid; i < 16 * 64; i += 128) sW0[i] = Wm0[i];
    for (int i = tid; i < 64 * 64; i += 128) sW1[i] = Wm1[i];
    if (tid < 64) { sb0[tid] = bm0[tid]; sb1[tid] = bm1[tid]; }
    __syncthreads();

    int e = blockIdx.x * 128 + tid;
    if (e >= E) return;

    float a[16];
#pragma unroll
    for (int k4 = 0; k4 < 4; k4++) {
        float4 v = *(const float4*)(ea + (size_t)e * 16 + k4 * 4);
        a[k4 * 4 + 0] = v.x; a[k4 * 4 + 1] = v.y;
        a[k4 * 4 + 2] = v.z; a[k4 * 4 + 3] = v.w;
    }

    float h1[64];
#pragma unroll
    for (int l4 = 0; l4 < 16; l4++) {
        float s0 = sb0[l4 * 4 + 0], s1 = sb0[l4 * 4 + 1];
        float s2 = sb0[l4 * 4 + 2], s3 = sb0[l4 * 4 + 3];
#pragma unroll
        for (int k = 0; k < 16; k++) {
            float4 w = *(const float4*)&sW0[k * 64 + l4 * 4];
            float av = a[k];
            s0 += av * w.x; s1 += av * w.y; s2 += av * w.z; s3 += av * w.w;
        }
        h1[l4 * 4 + 0] = fmaxf(s0, 0.f); h1[l4 * 4 + 1] = fmaxf(s1, 0.f);
        h1[l4 * 4 + 2] = fmaxf(s2, 0.f); h1[l4 * 4 + 3] = fmaxf(s3, 0.f);
    }

    __half* outp = g_e2h + (size_t)e * 64;
#pragma unroll
    for (int j4 = 0; j4 < 16; j4++) {
        float s0 = sb1[j4 * 4 + 0], s1 = sb1[j4 * 4 + 1];
        float s2 = sb1[j4 * 4 + 2], s3 = sb1[j4 * 4 + 3];
#pragma unroll
        for (int l = 0; l < 64; l++) {
            float4 w = *(const float4*)&sW1[l * 64 + j4 * 4];
            float hv = h1[l];
            s0 += hv * w.x; s1 += hv * w.y; s2 += hv * w.z; s3 += hv * w.w;
        }
        __half2 p0 = __floats2half2_rn(fmaxf(s0, 0.f), fmaxf(s1, 0.f));
        __half2 p1 = __floats2half2_rn(fmaxf(s2, 0.f), fmaxf(s3, 0.f));
        uint2 pk;
        pk.x = *(unsigned*)&p0; pk.y = *(unsigned*)&p1;
        *(uint2*)(outp + j4 * 4) = pk;
    }
}

// ---------------------------------------------------------------------------
// W GEMM (fp16 tensor cores): g_Wh[E,1024] = fp16(e2[E,64] @ Wm2[64,1024] + bm2)
// block 128M x 64N, K=64, 8 warps (4M x 2N, warp tile 32x32), m16n8k16.
// C staged through smem -> coalesced uint4 stores.
// ---------------------------------------------------------------------------
#define HPITCH 72   // halves per smem row (64 + 8 pad); 144B

__global__ __launch_bounds__(256) void k_wgemm(
    const float* __restrict__ bias, int E) {
    __shared__ __half sA[128 * HPITCH];   // [row][k]; reused as C stage
    __shared__ __half sB[64 * HPITCH];    // [n][k]  (Bt slice)
    __shared__ float  sbias[64];

    int bm = blockIdx.x * 128;
    int bn = blockIdx.y * 64;
    int tid = threadIdx.x;

    // stage A (128 rows x 64 halves) and B (64 rows x 64 halves)
    {
        int r = tid >> 3;          // 0..31
        int x = tid & 7;           // uint4 index within row
#pragma unroll
        for (int i = 0; i < 4; i++) {
            int row = r + i * 32;
            int rr = bm + row; if (rr >= E) rr = E - 1;
            uint4 va = *(const uint4*)(g_e2h + (size_t)rr * 64 + x * 8);
            *(uint4*)((char*)sA + row * 144 + x * 16) = va;
        }
#pragma unroll
        for (int i = 0; i < 2; i++) {
            int row = r + i * 32;
            uint4 vb = *(const uint4*)(g_Bt + (size_t)(bn + row) * 64 + x * 8);
            *(uint4*)((char*)sB + row * 144 + x * 16) = vb;
        }
        if (tid < 64) sbias[tid] = bias[bn + tid];
    }
    __syncthreads();

    int lane = tid & 31;
    int warp = tid >> 5;
    int wm = warp & 3;    // M strip of 32
    int wn = warp >> 2;   // N strip of 32
    int g = lane >> 2;    // groupID
    int c = lane & 3;     // threadID in group

    float acc[2][4][4];
#pragma unroll
    for (int mt = 0; mt < 2; mt++)
#pragma unroll
        for (int nt = 0; nt < 4; nt++)
#pragma unroll
            for (int q = 0; q < 4; q++) acc[mt][nt][q] = 0.f;

#pragma unroll
    for (int kk = 0; kk < 4; kk++) {
        int kb = kk * 16;
        unsigned a_[2][4];
#pragma unroll
        for (int mt = 0; mt < 2; mt++) {
            int r0 = wm * 32 + mt * 16 + g;
            a_[mt][0] = *(const unsigned*)&sA[r0 * HPITCH + kb + 2 * c];
            a_[mt][1] = *(const unsigned*)&sA[(r0 + 8) * HPITCH + kb + 2 * c];
            a_[mt][2] = *(const unsigned*)&sA[r0 * HPITCH + kb + 2 * c + 8];
            a_[mt][3] = *(const unsigned*)&sA[(r0 + 8) * HPITCH + kb + 2 * c + 8];
        }
        unsigned b_[4][2];
#pragma unroll
        for (int nt = 0; nt < 4; nt++) {
            int n0 = wn * 32 + nt * 8 + g;
            b_[nt][0] = *(const unsigned*)&sB[n0 * HPITCH + kb + 2 * c];
            b_[nt][1] = *(const unsigned*)&sB[n0 * HPITCH + kb + 2 * c + 8];
        }
#pragma unroll
        for (int mt = 0; mt < 2; mt++)
#pragma unroll
            for (int nt = 0; nt < 4; nt++) {
                asm volatile(
                    "mma.sync.aligned.m16n8k16.row.col.f32.f16.f16.f32 "
                    "{%0,%1,%2,%3}, {%4,%5,%6,%7}, {%8,%9}, {%0,%1,%2,%3};"
                    : "+f"(acc[mt][nt][0]), "+f"(acc[mt][nt][1]),
                      "+f"(acc[mt][nt][2]), "+f"(acc[mt][nt][3])
                    : "r"(a_[mt][0]), "r"(a_[mt][1]), "r"(a_[mt][2]), "r"(a_[mt][3]),
                      "r"(b_[nt][0]), "r"(b_[nt][1]));
            }
    }

    // all mma reads of sA are done; reuse sA as the C stage [128][HPITCH]
    __syncthreads();
#pragma unroll
    for (int nt = 0; nt < 4; nt++) {
        int col = wn * 32 + nt * 8 + 2 * c;
        float bx = sbias[col], by = sbias[col + 1];
#pragma unroll
        for (int mt = 0; mt < 2; mt++) {
            int row0 = wm * 32 + mt * 16 + g;
            __half2 v0 = __floats2half2_rn(acc[mt][nt][0] + bx, acc[mt][nt][1] + by);
            *(__half2*)&sA[row0 * HPITCH + col] = v0;
            __half2 v1 = __floats2half2_rn(acc[mt][nt][2] + bx, acc[mt][nt][3] + by);
            *(__half2*)&sA[(row0 + 8) * HPITCH + col] = v1;
        }
    }
    __syncthreads();

    // coalesced store: each row is 64 halves = 128B (8 threads x uint4)
    {
        int r = tid >> 3;          // 0..31
        int x = tid & 7;
#pragma unroll
        for (int i = 0; i < 4; i++) {
            int row = r + i * 32;
            int rr = bm + row;
            if (rr < E) {
                uint4 v = *(const uint4*)((char*)sA + row * 144 + x * 16);
                *(uint4*)(g_Wh + (size_t)rr * 1024 + bn + x * 8) = v;
            }
        }
    }
}

// ---------------------------------------------------------------------------
// message passing: agg[dst] += h[src] @ W_e   (one warp per edge, fp16 W)
// ---------------------------------------------------------------------------
__global__ __launch_bounds__(256) void k_msg(const int* __restrict__ ei, int selIn, int E) {
    int gw = (blockIdx.x * blockDim.x + threadIdx.x) >> 5;
    int lane = threadIdx.x & 31;
    if (gw >= E) return;
    const float* __restrict__ h = (selIn == 0) ? g_h0 : (selIn == 1) ? g_ha : g_hb;

    int2 sd = ((const int2*)ei)[gw];
    int src = sd.x, dst = sd.y;
    float hval = h[(size_t)src * 32 + lane];

    const uint4* __restrict__ W16 = (const uint4*)(g_Wh + (size_t)gw * 1024);
    float acc[8];
#pragma unroll
    for (int j = 0; j < 8; j++) acc[j] = 0.f;

#pragma unroll
    for (int i = 0; i < 4; i++) {
        uint4 w = W16[lane + 32 * i];
        float hs = __shfl_sync(0xffffffffu, hval, (lane >> 2) + 8 * i);
        const __half2* h2 = (const __half2*)&w;
#pragma unroll
        for (int j = 0; j < 4; j++) {
            float2 f = __half22float2(h2[j]);
            acc[2 * j]     += hs * f.x;
            acc[2 * j + 1] += hs * f.y;
        }
    }
#pragma unroll
    for (int m = 4; m <= 16; m <<= 1) {
#pragma unroll
        for (int j = 0; j < 8; j++)
            acc[j] += __shfl_xor_sync(0xffffffffu, acc[j], m);
    }
    int k = lane >> 2;
    float v = acc[0];
    if (k == 1) v = acc[1];
    if (k == 2) v = acc[2];
    if (k == 3) v = acc[3];
    if (k == 4) v = acc[4];
    if (k == 5) v = acc[5];
    if (k == 6) v = acc[6];
    if (k == 7) v = acc[7];
    atomicAdd(&g_agg[(size_t)dst * 32 + ((lane & 3) << 3) + k], v);
}

// ---------------------------------------------------------------------------
// node update: h_out = h_in @ root + bias + agg ; agg = 0   (warp per node)
// ---------------------------------------------------------------------------
__global__ __launch_bounds__(256) void k_update(
    int selIn, int selOut, const float* __restrict__ root,
    const float* __restrict__ bias, int N) {
    __shared__ float sroot[32 * 32];
    __shared__ float sb[32];
    int tid = threadIdx.x;
    for (int i = tid; i < 1024; i += 256) sroot[i] = root[i];
    if (tid < 32) sb[tid] = bias[tid];
    __syncthreads();

    int lane = tid & 31, w = tid >> 5;
    int n = blockIdx.x * 8 + w;
    if (n >= N) return;
    const float* __restrict__ hin = (selIn == 0) ? g_h0 : (selIn == 1) ? g_ha : g_hb;
    float* __restrict__ hout = (selOut == 1) ? g_ha : g_hb;

    float hv = hin[(size_t)n * 32 + lane];
    float acc = sb[lane] + g_agg[(size_t)n * 32 + lane];
    g_agg[(size_t)n * 32 + lane] = 0.0f;
#pragma unroll
    for (int k = 0; k < 32; k++)
        acc += __shfl_sync(0xffffffffu, hv, k) * sroot[k * 32 + lane];
    hout[(size_t)n * 32 + lane] = acc;
}

__global__ void k_zero(float* o, int n) {
    int i = blockIdx.x * blockDim.x + threadIdx.x;
    if (i < n) o[i] = 0.0f;
}

// ---------------------------------------------------------------------------
// readout: out = sum_n sigmoid(relu([h,h0]@Wi0+bi0)@Wi1+bi1) *
//                       (relu(h@Wj0+bj0)@Wj1+bj1)
// ---------------------------------------------------------------------------
__global__ __launch_bounds__(256) void k_readout(
    const float* __restrict__ Wi0, const float* __restrict__ bi0,
    const float* __restrict__ Wi1, const float* __restrict__ bi1,
    const float* __restrict__ Wj0, const float* __restrict__ bj0,
    const float* __restrict__ Wj1, const float* __restrict__ bj1,
    float* __restrict__ out, int N) {
    __shared__ float sW[64 * 128];
    __shared__ float sv1[128];
    __shared__ float sblock;
    int tid = threadIdx.x, lane = tid & 31, w = tid >> 5;
    int n = blockIdx.x * 8 + w;
    bool active = (n < N);

    for (int i = tid; i < 64 * 128; i += 256) sW[i] = Wi0[i];
    for (int i = tid; i < 128; i += 256) sv1[i] = Wi1[i];
    if (tid == 0) sblock = 0.f;
    __syncthreads();

    float za = 0.f, zb = 0.f;
    if (active) {
        za = g_ha[(size_t)n * 32 + lane];   // final h
        zb = g_h0[(size_t)n * 32 + lane];   // h0
    }

    float a0 = bi0[lane], a1 = bi0[lane + 32], a2 = bi0[lane + 64], a3 = bi0[lane + 96];
#pragma unroll
    for (int k = 0; k < 32; k++) {
        float zk = __shfl_sync(0xffffffffu, za, k);
        a0 += zk * sW[k * 128 + lane];
        a1 += zk * sW[k * 128 + lane + 32];
        a2 += zk * sW[k * 128 + lane + 64];
        a3 += zk * sW[k * 128 + lane + 96];
    }
#pragma unroll
    for (int k = 0; k < 32; k++) {
        float zk = __shfl_sync(0xffffffffu, zb, k);
        a0 += zk * sW[(k + 32) * 128 + lane];
        a1 += zk * sW[(k + 32) * 128 + lane + 32];
        a2 += zk * sW[(k + 32) * 128 + lane + 64];
        a3 += zk * sW[(k + 32) * 128 + lane + 96];
    }
    a0 = fmaxf(a0, 0.f); a1 = fmaxf(a1, 0.f); a2 = fmaxf(a2, 0.f); a3 = fmaxf(a3, 0.f);
    float gp = a0 * sv1[lane] + a1 * sv1[lane + 32] + a2 * sv1[lane + 64] + a3 * sv1[lane + 96];
#pragma unroll
    for (int s = 16; s > 0; s >>= 1) gp += __shfl_xor_sync(0xffffffffu, gp, s);
    float gate = 1.0f / (1.0f + expf(-(gp + bi1[0])));

    __syncthreads();   // done reading Wi0
    for (int i = tid; i < 32 * 128; i += 256) sW[i] = Wj0[i];
    for (int i = tid; i < 128; i += 256) sv1[i] = Wj1[i];
    __syncthreads();

    float b0 = bj0[lane], b1 = bj0[lane + 32], b2 = bj0[lane + 64], b3 = bj0[lane + 96];
#pragma unroll
    for (int k = 0; k < 32; k++) {
        float zk = __shfl_sync(0xffffffffu, za, k);
        b0 += zk * sW[k * 128 + lane];
        b1 += zk * sW[k * 128 + lane + 32];
        b2 += zk * sW[k * 128 + lane + 64];
        b3 += zk * sW[k * 128 + lane + 96];
    }
    b0 = fmaxf(b0, 0.f); b1 = fmaxf(b1, 0.f); b2 = fmaxf(b2, 0.f); b3 = fmaxf(b3, 0.f);
    float vp = b0 * sv1[lane] + b1 * sv1[lane + 32] + b2 * sv1[lane + 64] + b3 * sv1[lane + 96];
#pragma unroll
    for (int s = 16; s > 0; s >>= 1) vp += __shfl_xor_sync(0xffffffffu, vp, s);
    float val = vp + bj1[0];

    if (active && lane == 0) atomicAdd(&sblock, gate * val);
    __syncthreads();
    if (tid == 0) atomicAdd(out, sblock);
}

// ---------------------------------------------------------------------------
extern "C" void kernel_launch(void* const* d_in, const int* in_sizes, int n_in,
                              void* d_out, int out_size) {
    const float* x   = (const float*)d_in[0];
    const int*   ei  = (const int*)d_in[1];
    const float* ea  = (const float*)d_in[2];
    const float* Wm0 = (const float*)d_in[3];  const float* bm0 = (const float*)d_in[4];
    const float* Wm1 = (const float*)d_in[5];  const float* bm1 = (const float*)d_in[6];
    const float* Wm2 = (const float*)d_in[7];  const float* bm2 = (const float*)d_in[8];
    const float* root= (const float*)d_in[9];  const float* bias= (const float*)d_in[10];
    const float* Wi0 = (const float*)d_in[11]; const float* bi0 = (const float*)d_in[12];
    const float* Wi1 = (const float*)d_in[13]; const float* bi1 = (const float*)d_in[14];
    const float* Wj0 = (const float*)d_in[15]; const float* bj0 = (const float*)d_in[16];
    const float* Wj1 = (const float*)d_in[17]; const float* bj1 = (const float*)d_in[18];
    int N = in_sizes[0] / 16;
    int E = in_sizes[2] / 16;
    float* out = (float*)d_out;

    k_init<<<(N * 32 + 255) / 256, 256>>>(x, N);
    k_convB<<<(64 * 1024 + 255) / 256, 256>>>(Wm2);
    k_edge_mlp<<<(E + 127) / 128, 128>>>(ea, Wm0, bm0, Wm1, bm1, E);

    dim3 gg((E + 127) / 128, 16);
    k_wgemm<<<gg, 256>>>(bm2, E);

    int msgBlocks = (E + 7) / 8;
    int nodeBlocks = (N + 7) / 8;
    // iter 1: h0 -> ha
    k_msg<<<msgBlocks, 256>>>(ei, 0, E);
    k_update<<<nodeBlocks, 256>>>(0, 1, root, bias, N);
    // iter 2: ha -> hb
    k_msg<<<msgBlocks, 256>>>(ei, 1, E);
    k_update<<<nodeBlocks, 256>>>(1, 2, root, bias, N);
    // iter 3: hb -> ha
    k_msg<<<msgBlocks, 256>>>(ei, 2, E);
    k_update<<<nodeBlocks, 256>>>(2, 1, root, bias, N);

    k_zero<<<1, 32>>>(out, out_size);
    k_readout<<<nodeBlocks, 256>>>(Wi0, bi0, Wi1, bi1, Wj0, bj0, Wj1, bj1, out, N);
}

// round 9
// speedup vs baseline: 1.2708x; 1.0324x over previous
#include <cuda_runtime.h>
#include <cuda_fp16.h>
#include <math.h>
#include <stdint.h>

#define MAXE 400000
#define MAXN 50000

// Scratch (device globals: the sanctioned alloc-free workaround)
__device__ __half g_e2h[(size_t)MAXE * 64];    // 51 MB: edge MLP output (fp16)
__device__ __half g_Bt[64 * 1024];             // Wm2 transposed [n][k], fp16
__device__ __half g_Wh[(size_t)MAXE * 1024];   // 819 MB: per-edge 32x32 matrices (fp16)
__device__ float  g_h0[(size_t)MAXN * 32];
__device__ float  g_ha[(size_t)MAXN * 32];
__device__ float  g_hb[(size_t)MAXN * 32];
__device__ float  g_agg[(size_t)MAXN * 32];

// ---------------------------------------------------------------------------
// init: h0 = [x, zeros], agg = 0
// ---------------------------------------------------------------------------
__global__ void k_init(const float* __restrict__ x, int N) {
    int i = blockIdx.x * blockDim.x + threadIdx.x;
    if (i < N * 32) {
        int n = i >> 5, o = i & 31;
        g_h0[i] = (o < 16) ? x[n * 16 + o] : 0.0f;
        g_agg[i] = 0.0f;
    }
}

// ---------------------------------------------------------------------------
// convB: g_Bt[n][k] = fp16(Wm2[k][n])   (64x1024 -> 1024x64)
// ---------------------------------------------------------------------------
__global__ void k_convB(const float* __restrict__ B) {
    int i = blockIdx.x * blockDim.x + threadIdx.x;
    if (i < 64 * 1024) {
        int n = i >> 6, k = i & 63;
        g_Bt[i] = __float2half_rn(B[k * 1024 + n]);
    }
}

// ---------------------------------------------------------------------------
// edge MLP: e2 = relu(relu(ea@Wm0+bm0)@Wm1+bm1)  (fp32 math, fp16 output)
// ---------------------------------------------------------------------------
__global__ __launch_bounds__(128) void k_edge_mlp(
    const float* __restrict__ ea,
    const float* __restrict__ Wm0, const float* __restrict__ bm0,
    const float* __restrict__ Wm1, const float* __restrict__ bm1, int E) {
    __shared__ float sW0[16 * 64];
    __shared__ float sW1[64 * 64];
    __shared__ float sb0[64], sb1[64];
    int tid = threadIdx.x;
    for (int i = tid; i < 16 * 64; i += 128) sW0[i] = Wm0[i];
    for (int i = tid; i < 64 * 64; i += 128) sW1[i] = Wm1[i];
    if (tid < 64) { sb0[tid] = bm0[tid]; sb1[tid] = bm1[tid]; }
    __syncthreads();

    int e = blockIdx.x * 128 + tid;
    if (e >= E) return;

    float a[16];
#pragma unroll
    for (int k4 = 0; k4 < 4; k4++) {
        float4 v = *(const float4*)(ea + (size_t)e * 16 + k4 * 4);
        a[k4 * 4 + 0] = v.x; a[k4 * 4 + 1] = v.y;
        a[k4 * 4 + 2] = v.z; a[k4 * 4 + 3] = v.w;
    }

    float h1[64];
#pragma unroll
    for (int l4 = 0; l4 < 16; l4++) {
        float s0 = sb0[l4 * 4 + 0], s1 = sb0[l4 * 4 + 1];
        float s2 = sb0[l4 * 4 + 2], s3 = sb0[l4 * 4 + 3];
#pragma unroll
        for (int k = 0; k < 16; k++) {
            float4 w = *(const float4*)&sW0[k * 64 + l4 * 4];
            float av = a[k];
            s0 += av * w.x; s1 += av * w.y; s2 += av * w.z; s3 += av * w.w;
        }
        h1[l4 * 4 + 0] = fmaxf(s0, 0.f); h1[l4 * 4 + 1] = fmaxf(s1, 0.f);
        h1[l4 * 4 + 2] = fmaxf(s2, 0.f); h1[l4 * 4 + 3] = fmaxf(s3, 0.f);
    }

    __half* outp = g_e2h + (size_t)e * 64;
#pragma unroll
    for (int j4 = 0; j4 < 16; j4++) {
        float s0 = sb1[j4 * 4 + 0], s1 = sb1[j4 * 4 + 1];
        float s2 = sb1[j4 * 4 + 2], s3 = sb1[j4 * 4 + 3];
#pragma unroll
        for (int l = 0; l < 64; l++) {
            float4 w = *(const float4*)&sW1[l * 64 + j4 * 4];
            float hv = h1[l];
            s0 += hv * w.x; s1 += hv * w.y; s2 += hv * w.z; s3 += hv * w.w;
        }
        __half2 p0 = __floats2half2_rn(fmaxf(s0, 0.f), fmaxf(s1, 0.f));
        __half2 p1 = __floats2half2_rn(fmaxf(s2, 0.f), fmaxf(s3, 0.f));
        uint2 pk;
        pk.x = *(unsigned*)&p0; pk.y = *(unsigned*)&p1;
        *(uint2*)(outp + j4 * 4) = pk;
    }
}

// ---------------------------------------------------------------------------
// W GEMM (fp16 tensor cores): g_Wh[E,1024] = fp16(e2[E,64] @ Wm2[64,1024] + bm2)
// CTA = 128 rows x 512 cols (8 chunks of 64), A staged ONCE.
// 8 warps (4M x 2N, warp tile 32x32), m16n8k16; C staged in smem -> uint4 stores
// ---------------------------------------------------------------------------
#define HPITCH 72   // halves per smem row (64 + 8 pad); 144B

__global__ __launch_bounds__(256) void k_wgemm(
    const float* __restrict__ bias, int E) {
    __shared__ __half sA[128 * HPITCH];   // A tile, persistent
    __shared__ __half sB[64 * HPITCH];    // B chunk [n][k]
    __shared__ __half sC[128 * HPITCH];   // C stage
    __shared__ float  sbias[64];

    int bm = blockIdx.x * 128;
    int bn0 = blockIdx.y * 512;
    int tid = threadIdx.x;
    int r = tid >> 3;          // 0..31
    int x = tid & 7;           // uint4 index within 64-half row

    // stage A once (128 rows x 64 halves)
#pragma unroll
    for (int i = 0; i < 4; i++) {
        int row = r + i * 32;
        int rr = bm + row; if (rr >= E) rr = E - 1;
        uint4 va = *(const uint4*)(g_e2h + (size_t)rr * 64 + x * 8);
        *(uint4*)((char*)sA + row * 144 + x * 16) = va;
    }

    int lane = tid & 31;
    int warp = tid >> 5;
    int wm = warp & 3;    // M strip of 32
    int wn = warp >> 2;   // N strip of 32
    int g = lane >> 2;
    int c = lane & 3;

#pragma unroll 1
    for (int ch = 0; ch < 8; ch++) {
        int bn = bn0 + ch * 64;

        // stage B chunk: 64 rows x 64 halves = 512 uint4 (256 thr x 2)
#pragma unroll
        for (int i = 0; i < 2; i++) {
            int row = r + i * 32;
            uint4 vb = *(const uint4*)(g_Bt + (size_t)(bn + row) * 64 + x * 8);
            *(uint4*)((char*)sB + row * 144 + x * 16) = vb;
        }
        if (tid < 64) sbias[tid] = bias[bn + tid];
        __syncthreads();

        float acc[2][4][4];
#pragma unroll
        for (int mt = 0; mt < 2; mt++)
#pragma unroll
            for (int nt = 0; nt < 4; nt++)
#pragma unroll
                for (int q = 0; q < 4; q++) acc[mt][nt][q] = 0.f;

#pragma unroll
        for (int kk = 0; kk < 4; kk++) {
            int kb = kk * 16;
            unsigned a_[2][4];
#pragma unroll
            for (int mt = 0; mt < 2; mt++) {
                int r0 = wm * 32 + mt * 16 + g;
                a_[mt][0] = *(const unsigned*)&sA[r0 * HPITCH + kb + 2 * c];
                a_[mt][1] = *(const unsigned*)&sA[(r0 + 8) * HPITCH + kb + 2 * c];
                a_[mt][2] = *(const unsigned*)&sA[r0 * HPITCH + kb + 2 * c + 8];
                a_[mt][3] = *(const unsigned*)&sA[(r0 + 8) * HPITCH + kb + 2 * c + 8];
            }
            unsigned b_[4][2];
#pragma unroll
            for (int nt = 0; nt < 4; nt++) {
                int n0 = wn * 32 + nt * 8 + g;
                b_[nt][0] = *(const unsigned*)&sB[n0 * HPITCH + kb + 2 * c];
                b_[nt][1] = *(const unsigned*)&sB[n0 * HPITCH + kb + 2 * c + 8];
            }
#pragma unroll
            for (int mt = 0; mt < 2; mt++)
#pragma unroll
                for (int nt = 0; nt < 4; nt++) {
                    asm volatile(
                        "mma.sync.aligned.m16n8k16.row.col.f32.f16.f16.f32 "
                        "{%0,%1,%2,%3}, {%4,%5,%6,%7}, {%8,%9}, {%0,%1,%2,%3};"
                        : "+f"(acc[mt][nt][0]), "+f"(acc[mt][nt][1]),
                          "+f"(acc[mt][nt][2]), "+f"(acc[mt][nt][3])
                        : "r"(a_[mt][0]), "r"(a_[mt][1]), "r"(a_[mt][2]), "r"(a_[mt][3]),
                          "r"(b_[nt][0]), "r"(b_[nt][1]));
                }
        }

        // write acc -> sC (bias added)
#pragma unroll
        for (int nt = 0; nt < 4; nt++) {
            int col = wn * 32 + nt * 8 + 2 * c;
            float bx = sbias[col], by = sbias[col + 1];
#pragma unroll
            for (int mt = 0; mt < 2; mt++) {
                int row0 = wm * 32 + mt * 16 + g;
                __half2 v0 = __floats2half2_rn(acc[mt][nt][0] + bx, acc[mt][nt][1] + by);
                *(__half2*)&sC[row0 * HPITCH + col] = v0;
                __half2 v1 = __floats2half2_rn(acc[mt][nt][2] + bx, acc[mt][nt][3] + by);
                *(__half2*)&sC[(row0 + 8) * HPITCH + col] = v1;
            }
        }
        __syncthreads();

        // coalesced store: 128 rows x 64 halves (8 threads x uint4 per row)
#pragma unroll
        for (int i = 0; i < 4; i++) {
            int row = r + i * 32;
            int rr = bm + row;
            if (rr < E) {
                uint4 v = *(const uint4*)((char*)sC + row * 144 + x * 16);
                *(uint4*)(g_Wh + (size_t)rr * 1024 + bn + x * 8) = v;
            }
        }
    }
}

// ---------------------------------------------------------------------------
// message passing: agg[dst] += h[src] @ W_e   (one warp per edge, fp16 W)
// ---------------------------------------------------------------------------
__global__ __launch_bounds__(256) void k_msg(const int* __restrict__ ei, int selIn, int E) {
    int gw = (blockIdx.x * blockDim.x + threadIdx.x) >> 5;
    int lane = threadIdx.x & 31;
    if (gw >= E) return;
    const float* __restrict__ h = (selIn == 0) ? g_h0 : (selIn == 1) ? g_ha : g_hb;

    int2 sd = ((const int2*)ei)[gw];
    int src = sd.x, dst = sd.y;
    float hval = h[(size_t)src * 32 + lane];

    const uint4* __restrict__ W16 = (const uint4*)(g_Wh + (size_t)gw * 1024);
    float acc[8];
#pragma unroll
    for (int j = 0; j < 8; j++) acc[j] = 0.f;

#pragma unroll
    for (int i = 0; i < 4; i++) {
        uint4 w = W16[lane + 32 * i];
        float hs = __shfl_sync(0xffffffffu, hval, (lane >> 2) + 8 * i);
        const __half2* h2 = (const __half2*)&w;
#pragma unroll
        for (int j = 0; j < 4; j++) {
            float2 f = __half22float2(h2[j]);
            acc[2 * j]     += hs * f.x;
            acc[2 * j + 1] += hs * f.y;
        }
    }
#pragma unroll
    for (int m = 4; m <= 16; m <<= 1) {
#pragma unroll
        for (int j = 0; j < 8; j++)
            acc[j] += __shfl_xor_sync(0xffffffffu, acc[j], m);
    }
    int k = lane >> 2;
    float v = acc[0];
    if (k == 1) v = acc[1];
    if (k == 2) v = acc[2];
    if (k == 3) v = acc[3];
    if (k == 4) v = acc[4];
    if (k == 5) v = acc[5];
    if (k == 6) v = acc[6];
    if (k == 7) v = acc[7];
    atomicAdd(&g_agg[(size_t)dst * 32 + ((lane & 3) << 3) + k], v);
}

// ---------------------------------------------------------------------------
// node update: h_out = h_in @ root + bias + agg ; agg = 0   (warp per node)
// ---------------------------------------------------------------------------
__global__ __launch_bounds__(256) void k_update(
    int selIn, int selOut, const float* __restrict__ root,
    const float* __restrict__ bias, int N) {
    __shared__ float sroot[32 * 32];
    __shared__ float sb[32];
    int tid = threadIdx.x;
    for (int i = tid; i < 1024; i += 256) sroot[i] = root[i];
    if (tid < 32) sb[tid] = bias[tid];
    __syncthreads();

    int lane = tid & 31, w = tid >> 5;
    int n = blockIdx.x * 8 + w;
    if (n >= N) return;
    const float* __restrict__ hin = (selIn == 0) ? g_h0 : (selIn == 1) ? g_ha : g_hb;
    float* __restrict__ hout = (selOut == 1) ? g_ha : g_hb;

    float hv = hin[(size_t)n * 32 + lane];
    float acc = sb[lane] + g_agg[(size_t)n * 32 + lane];
    g_agg[(size_t)n * 32 + lane] = 0.0f;
#pragma unroll
    for (int k = 0; k < 32; k++)
        acc += __shfl_sync(0xffffffffu, hv, k) * sroot[k * 32 + lane];
    hout[(size_t)n * 32 + lane] = acc;
}

__global__ void k_zero(float* o, int n) {
    int i = blockIdx.x * blockDim.x + threadIdx.x;
    if (i < n) o[i] = 0.0f;
}

// ---------------------------------------------------------------------------
// readout: out = sum_n sigmoid(relu([h,h0]@Wi0+bi0)@Wi1+bi1) *
//                       (relu(h@Wj0+bj0)@Wj1+bj1)
// ---------------------------------------------------------------------------
__global__ __launch_bounds__(256) void k_readout(
    const float* __restrict__ Wi0, const float* __restrict__ bi0,
    const float* __restrict__ Wi1, const float* __restrict__ bi1,
    const float* __restrict__ Wj0, const float* __restrict__ bj0,
    const float* __restrict__ Wj1, const float* __restrict__ bj1,
    float* __restrict__ out, int N) {
    __shared__ float sW[64 * 128];
    __shared__ float sv1[128];
    __shared__ float sblock;
    int tid = threadIdx.x, lane = tid & 31, w = tid >> 5;
    int n = blockIdx.x * 8 + w;
    bool active = (n < N);

    for (int i = tid; i < 64 * 128; i += 256) sW[i] = Wi0[i];
    for (int i = tid; i < 128; i += 256) sv1[i] = Wi1[i];
    if (tid == 0) sblock = 0.f;
    __syncthreads();

    float za = 0.f, zb = 0.f;
    if (active) {
        za = g_ha[(size_t)n * 32 + lane];   // final h
        zb = g_h0[(size_t)n * 32 + lane];   // h0
    }

    float a0 = bi0[lane], a1 = bi0[lane + 32], a2 = bi0[lane + 64], a3 = bi0[lane + 96];
#pragma unroll
    for (int k = 0; k < 32; k++) {
        float zk = __shfl_sync(0xffffffffu, za, k);
        a0 += zk * sW[k * 128 + lane];
        a1 += zk * sW[k * 128 + lane + 32];
        a2 += zk * sW[k * 128 + lane + 64];
        a3 += zk * sW[k * 128 + lane + 96];
    }
#pragma unroll
    for (int k = 0; k < 32; k++) {
        float zk = __shfl_sync(0xffffffffu, zb, k);
        a0 += zk * sW[(k + 32) * 128 + lane];
        a1 += zk * sW[(k + 32) * 128 + lane + 32];
        a2 += zk * sW[(k + 32) * 128 + lane + 64];
        a3 += zk * sW[(k + 32) * 128 + lane + 96];
    }
    a0 = fmaxf(a0, 0.f); a1 = fmaxf(a1, 0.f); a2 = fmaxf(a2, 0.f); a3 = fmaxf(a3, 0.f);
    float gp = a0 * sv1[lane] + a1 * sv1[lane + 32] + a2 * sv1[lane + 64] + a3 * sv1[lane + 96];
#pragma unroll
    for (int s = 16; s > 0; s >>= 1) gp += __shfl_xor_sync(0xffffffffu, gp, s);
    float gate = 1.0f / (1.0f + expf(-(gp + bi1[0])));

    __syncthreads();   // done reading Wi0
    for (int i = tid; i < 32 * 128; i += 256) sW[i] = Wj0[i];
    for (int i = tid; i < 128; i += 256) sv1[i] = Wj1[i];
    __syncthreads();

    float b0 = bj0[lane], b1 = bj0[lane + 32], b2 = bj0[lane + 64], b3 = bj0[lane + 96];
#pragma unroll
    for (int k = 0; k < 32; k++) {
        float zk = __shfl_sync(0xffffffffu, za, k);
        b0 += zk * sW[k * 128 + lane];
        b1 += zk * sW[k * 128 + lane + 32];
        b2 += zk * sW[k * 128 + lane + 64];
        b3 += zk * sW[k * 128 + lane + 96];
    }
    b0 = fmaxf(b0, 0.f); b1 = fmaxf(b1, 0.f); b2 = fmaxf(b2, 0.f); b3 = fmaxf(b3, 0.f);
    float vp = b0 * sv1[lane] + b1 * sv1[lane + 32] + b2 * sv1[lane + 64] + b3 * sv1[lane + 96];
#pragma unroll
    for (int s = 16; s > 0; s >>= 1) vp += __shfl_xor_sync(0xffffffffu, vp, s);
    float val = vp + bj1[0];

    if (active && lane == 0) atomicAdd(&sblock, gate * val);
    __syncthreads();
    if (tid == 0) atomicAdd(out, sblock);
}

// ---------------------------------------------------------------------------
extern "C" void kernel_launch(void* const* d_in, const int* in_sizes, int n_in,
                              void* d_out, int out_size) {
    const float* x   = (const float*)d_in[0];
    const int*   ei  = (const int*)d_in[1];
    const float* ea  = (const float*)d_in[2];
    const float* Wm0 = (const float*)d_in[3];  const float* bm0 = (const float*)d_in[4];
    const float* Wm1 = (const float*)d_in[5];  const float* bm1 = (const float*)d_in[6];
    const float* Wm2 = (const float*)d_in[7];  const float* bm2 = (const float*)d_in[8];
    const float* root= (const float*)d_in[9];  const float* bias= (const float*)d_in[10];
    const float* Wi0 = (const float*)d_in[11]; const float* bi0 = (const float*)d_in[12];
    const float* Wi1 = (const float*)d_in[13]; const float* bi1 = (const float*)d_in[14];
    const float* Wj0 = (const float*)d_in[15]; const float* bj0 = (const float*)d_in[16];
    const float* Wj1 = (const float*)d_in[17]; const float* bj1 = (const float*)d_in[18];
    int N = in_sizes[0] / 16;
    int E = in_sizes[2] / 16;
    float* out = (float*)d_out;

    k_init<<<(N * 32 + 255) / 256, 256>>>(x, N);
    k_convB<<<(64 * 1024 + 255) / 256, 256>>>(Wm2);
    k_edge_mlp<<<(E + 127) / 128, 128>>>(ea, Wm0, bm0, Wm1, bm1, E);

    dim3 gg((E + 127) / 128, 2);
    k_wgemm<<<gg, 256>>>(bm2, E);

    int msgBlocks = (E + 7) / 8;
    int nodeBlocks = (N + 7) / 8;
    // iter 1: h0 -> ha
    k_msg<<<msgBlocks, 256>>>(ei, 0, E);
    k_update<<<nodeBlocks, 256>>>(0, 1, root, bias, N);
    // iter 2: ha -> hb
    k_msg<<<msgBlocks, 256>>>(ei, 1, E);
    k_update<<<nodeBlocks, 256>>>(1, 2, root, bias, N);
    // iter 3: hb -> ha
    k_msg<<<msgBlocks, 256>>>(ei, 2, E);
    k_update<<<nodeBlocks, 256>>>(2, 1, root, bias, N);

    k_zero<<<1, 32>>>(out, out_size);
    k_readout<<<nodeBlocks, 256>>>(Wi0, bi0, Wi1, bi1, Wj0, bj0, Wj1, bj1, out, N);
}

// round 10
// speedup vs baseline: 1.3130x; 1.0332x over previous
#include <cuda_runtime.h>
#include <cuda_fp16.h>
#include <math.h>
#include <stdint.h>

#define MAXE 400000
#define MAXN 50000

// Scratch (device globals: the sanctioned alloc-free workaround)
__device__ __half g_e2h[(size_t)MAXE * 64];    // 51 MB: edge MLP output (fp16)
__device__ __half g_Bt[64 * 1024];             // Wm2 transposed [n][k], fp16
__device__ __half g_Wh[(size_t)MAXE * 1024];   // 819 MB: per-edge W (PERMUTED layout)
__device__ float  g_h0[(size_t)MAXN * 32];
__device__ float  g_ha[(size_t)MAXN * 32];
__device__ float  g_hb[(size_t)MAXN * 32];
__device__ float  g_agg[(size_t)MAXN * 32];

// Permuted W layout: W'[e][h*32 + c*8 + nt*2 + b] = W_e[h][nt*8 + 2c + b]
//   (h in 0..31, c in 0..3, nt in 0..3, b in 0..1)

// ---------------------------------------------------------------------------
// init: h0 = [x, zeros], agg = 0
// ---------------------------------------------------------------------------
__global__ void k_init(const float* __restrict__ x, int N) {
    int i = blockIdx.x * blockDim.x + threadIdx.x;
    if (i < N * 32) {
        int n = i >> 5, o = i & 31;
        g_h0[i] = (o < 16) ? x[n * 16 + o] : 0.0f;
        g_agg[i] = 0.0f;
    }
}

// ---------------------------------------------------------------------------
// convB: g_Bt[n][k] = fp16(Wm2[k][n])   (64x1024 -> 1024x64)
// ---------------------------------------------------------------------------
__global__ void k_convB(const float* __restrict__ B) {
    int i = blockIdx.x * blockDim.x + threadIdx.x;
    if (i < 64 * 1024) {
        int n = i >> 6, k = i & 63;
        g_Bt[i] = __float2half_rn(B[k * 1024 + n]);
    }
}

// ---------------------------------------------------------------------------
// edge MLP: e2 = relu(relu(ea@Wm0+bm0)@Wm1+bm1)  (fp32 math, fp16 output)
// ---------------------------------------------------------------------------
__global__ __launch_bounds__(128) void k_edge_mlp(
    const float* __restrict__ ea,
    const float* __restrict__ Wm0, const float* __restrict__ bm0,
    const float* __restrict__ Wm1, const float* __restrict__ bm1, int E) {
    __shared__ float sW0[16 * 64];
    __shared__ float sW1[64 * 64];
    __shared__ float sb0[64], sb1[64];
    int tid = threadIdx.x;
    for (int i = tid; i < 16 * 64; i += 128) sW0[i] = Wm0[i];
    for (int i = tid; i < 64 * 64; i += 128) sW1[i] = Wm1[i];
    if (tid < 64) { sb0[tid] = bm0[tid]; sb1[tid] = bm1[tid]; }
    __syncthreads();

    int e = blockIdx.x * 128 + tid;
    if (e >= E) return;

    float a[16];
#pragma unroll
    for (int k4 = 0; k4 < 4; k4++) {
        float4 v = *(const float4*)(ea + (size_t)e * 16 + k4 * 4);
        a[k4 * 4 + 0] = v.x; a[k4 * 4 + 1] = v.y;
        a[k4 * 4 + 2] = v.z; a[k4 * 4 + 3] = v.w;
    }

    float h1[64];
#pragma unroll
    for (int l4 = 0; l4 < 16; l4++) {
        float s0 = sb0[l4 * 4 + 0], s1 = sb0[l4 * 4 + 1];
        float s2 = sb0[l4 * 4 + 2], s3 = sb0[l4 * 4 + 3];
#pragma unroll
        for (int k = 0; k < 16; k++) {
            float4 w = *(const float4*)&sW0[k * 64 + l4 * 4];
            float av = a[k];
            s0 += av * w.x; s1 += av * w.y; s2 += av * w.z; s3 += av * w.w;
        }
        h1[l4 * 4 + 0] = fmaxf(s0, 0.f); h1[l4 * 4 + 1] = fmaxf(s1, 0.f);
        h1[l4 * 4 + 2] = fmaxf(s2, 0.f); h1[l4 * 4 + 3] = fmaxf(s3, 0.f);
    }

    __half* outp = g_e2h + (size_t)e * 64;
#pragma unroll
    for (int j4 = 0; j4 < 16; j4++) {
        float s0 = sb1[j4 * 4 + 0], s1 = sb1[j4 * 4 + 1];
        float s2 = sb1[j4 * 4 + 2], s3 = sb1[j4 * 4 + 3];
#pragma unroll
        for (int l = 0; l < 64; l++) {
            float4 w = *(const float4*)&sW1[l * 64 + j4 * 4];
            float hv = h1[l];
            s0 += hv * w.x; s1 += hv * w.y; s2 += hv * w.z; s3 += hv * w.w;
        }
        __half2 p0 = __floats2half2_rn(fmaxf(s0, 0.f), fmaxf(s1, 0.f));
        __half2 p1 = __floats2half2_rn(fmaxf(s2, 0.f), fmaxf(s3, 0.f));
        uint2 pk;
        pk.x = *(unsigned*)&p0; pk.y = *(unsigned*)&p1;
        *(uint2*)(outp + j4 * 4) = pk;
    }
}

// ---------------------------------------------------------------------------
// W GEMM (fp16 tensor cores): permuted-layout W from e2[E,64] @ Wm2 + bm2
// CTA = 128 rows x 512 cols (8 chunks of 64), A staged ONCE.
// 8 warps (4M x 2N, warp tile 32x32), m16n8k16; fragments stored DIRECTLY.
// ---------------------------------------------------------------------------
#define HPITCH 72   // halves per smem row (64 + 8 pad); 144B

__global__ __launch_bounds__(256) void k_wgemm(
    const float* __restrict__ bias, int E) {
    __shared__ __half sA[128 * HPITCH];   // A tile, persistent
    __shared__ __half sB[64 * HPITCH];    // B chunk [n][k]
    __shared__ float  sbias[64];

    int bm = blockIdx.x * 128;
    int bn0 = blockIdx.y * 512;
    int tid = threadIdx.x;
    int r = tid >> 3;          // 0..31
    int x = tid & 7;           // uint4 index within 64-half row

    // stage A once (128 rows x 64 halves)
#pragma unroll
    for (int i = 0; i < 4; i++) {
        int row = r + i * 32;
        int rr = bm + row; if (rr >= E) rr = E - 1;
        uint4 va = *(const uint4*)(g_e2h + (size_t)rr * 64 + x * 8);
        *(uint4*)((char*)sA + row * 144 + x * 16) = va;
    }

    int lane = tid & 31;
    int warp = tid >> 5;
    int wm = warp & 3;    // M strip of 32
    int wn = warp >> 2;   // N strip of 32
    int g = lane >> 2;
    int c = lane & 3;

#pragma unroll 1
    for (int ch = 0; ch < 8; ch++) {
        int bn = bn0 + ch * 64;

        // stage B chunk: 64 rows x 64 halves = 512 uint4 (256 thr x 2)
#pragma unroll
        for (int i = 0; i < 2; i++) {
            int row = r + i * 32;
            uint4 vb = *(const uint4*)(g_Bt + (size_t)(bn + row) * 64 + x * 8);
            *(uint4*)((char*)sB + row * 144 + x * 16) = vb;
        }
        if (tid < 64) sbias[tid] = bias[bn + tid];
        __syncthreads();

        float acc[2][4][4];
#pragma unroll
        for (int mt = 0; mt < 2; mt++)
#pragma unroll
            for (int nt = 0; nt < 4; nt++)
#pragma unroll
                for (int q = 0; q < 4; q++) acc[mt][nt][q] = 0.f;

#pragma unroll
        for (int kk = 0; kk < 4; kk++) {
            int kb = kk * 16;
            unsigned a_[2][4];
#pragma unroll
            for (int mt = 0; mt < 2; mt++) {
                int r0 = wm * 32 + mt * 16 + g;
                a_[mt][0] = *(const unsigned*)&sA[r0 * HPITCH + kb + 2 * c];
                a_[mt][1] = *(const unsigned*)&sA[(r0 + 8) * HPITCH + kb + 2 * c];
                a_[mt][2] = *(const unsigned*)&sA[r0 * HPITCH + kb + 2 * c + 8];
                a_[mt][3] = *(const unsigned*)&sA[(r0 + 8) * HPITCH + kb + 2 * c + 8];
            }
            unsigned b_[4][2];
#pragma unroll
            for (int nt = 0; nt < 4; nt++) {
                int n0 = wn * 32 + nt * 8 + g;
                b_[nt][0] = *(const unsigned*)&sB[n0 * HPITCH + kb + 2 * c];
                b_[nt][1] = *(const unsigned*)&sB[n0 * HPITCH + kb + 2 * c + 8];
            }
#pragma unroll
            for (int mt = 0; mt < 2; mt++)
#pragma unroll
                for (int nt = 0; nt < 4; nt++) {
                    asm volatile(
                        "mma.sync.aligned.m16n8k16.row.col.f32.f16.f16.f32 "
                        "{%0,%1,%2,%3}, {%4,%5,%6,%7}, {%8,%9}, {%0,%1,%2,%3};"
                        : "+f"(acc[mt][nt][0]), "+f"(acc[mt][nt][1]),
                          "+f"(acc[mt][nt][2]), "+f"(acc[mt][nt][3])
                        : "r"(a_[mt][0]), "r"(a_[mt][1]), "r"(a_[mt][2]), "r"(a_[mt][3]),
                          "r"(b_[nt][0]), "r"(b_[nt][1]));
                }
        }

        // direct permuted store: per (mt,q) one uint4 (nt pairs) per thread
        // dest halves: W'[e][h*32 + c*8 + nt*2 + b], h = (bn + wn*32)/32
        {
            int hcol = (bn + wn * 32);   // = h*32
            float bb[4][2];
#pragma unroll
            for (int nt = 0; nt < 4; nt++) {
                int col = wn * 32 + nt * 8 + 2 * c;
                bb[nt][0] = sbias[col];
                bb[nt][1] = sbias[col + 1];
            }
#pragma unroll
            for (int mt = 0; mt < 2; mt++) {
#pragma unroll
                for (int q = 0; q < 2; q++) {
                    int er = bm + wm * 32 + mt * 16 + q * 8 + g;
                    if (er < E) {
                        __half2 v[4];
#pragma unroll
                        for (int nt = 0; nt < 4; nt++)
                            v[nt] = __floats2half2_rn(acc[mt][nt][2 * q] + bb[nt][0],
                                                      acc[mt][nt][2 * q + 1] + bb[nt][1]);
                        uint4 pk;
                        pk.x = *(unsigned*)&v[0]; pk.y = *(unsigned*)&v[1];
                        pk.z = *(unsigned*)&v[2]; pk.w = *(unsigned*)&v[3];
                        *(uint4*)(g_Wh + (size_t)er * 1024 + hcol + c * 8) = pk;
                    }
                }
            }
        }
        __syncthreads();   // all warps done with sB before restage
    }
}

// ---------------------------------------------------------------------------
// message passing: agg[dst] += h[src] @ W_e   (one warp per edge, permuted fp16 W)
// uint4 chunk t = lane + 32*i holds h = t/4 fixed, c = t%4;
// halves j = nt*2+b -> o = nt*8 + 2c + b
// ---------------------------------------------------------------------------
__global__ __launch_bounds__(256) void k_msg(const int* __restrict__ ei, int selIn, int E) {
    int gw = (blockIdx.x * blockDim.x + threadIdx.x) >> 5;
    int lane = threadIdx.x & 31;
    if (gw >= E) return;
    const float* __restrict__ h = (selIn == 0) ? g_h0 : (selIn == 1) ? g_ha : g_hb;

    int2 sd = ((const int2*)ei)[gw];
    int src = sd.x, dst = sd.y;
    float hval = h[(size_t)src * 32 + lane];

    const uint4* __restrict__ W16 = (const uint4*)(g_Wh + (size_t)gw * 1024);
    float acc[8];
#pragma unroll
    for (int j = 0; j < 8; j++) acc[j] = 0.f;

#pragma unroll
    for (int i = 0; i < 4; i++) {
        uint4 w = W16[lane + 32 * i];
        float hs = __shfl_sync(0xffffffffu, hval, (lane >> 2) + 8 * i);
        const __half2* h2 = (const __half2*)&w;
#pragma unroll
        for (int j = 0; j < 4; j++) {
            float2 f = __half22float2(h2[j]);
            acc[2 * j]     += hs * f.x;    // (nt=j, b=0)
            acc[2 * j + 1] += hs * f.y;    // (nt=j, b=1)
        }
    }
    // reduce across the 8 lanes sharing c = lane%4 (strides 4, 8, 16)
#pragma unroll
    for (int m = 4; m <= 16; m <<= 1) {
#pragma unroll
        for (int j = 0; j < 8; j++)
            acc[j] += __shfl_xor_sync(0xffffffffu, acc[j], m);
    }
    // lane (c = lane%4, k = lane>>2) writes o = (k>>1)*8 + 2c + (k&1), value acc[k]
    int k = lane >> 2;
    float v = acc[0];
    if (k == 1) v = acc[1];
    if (k == 2) v = acc[2];
    if (k == 3) v = acc[3];
    if (k == 4) v = acc[4];
    if (k == 5) v = acc[5];
    if (k == 6) v = acc[6];
    if (k == 7) v = acc[7];
    int o = ((k >> 1) << 3) + ((lane & 3) << 1) + (k & 1);
    atomicAdd(&g_agg[(size_t)dst * 32 + o], v);
}

// ---------------------------------------------------------------------------
// node update: h_out = h_in @ root + bias + agg ; agg = 0   (warp per node)
// ---------------------------------------------------------------------------
__global__ __launch_bounds__(256) void k_update(
    int selIn, int selOut, const float* __restrict__ root,
    const float* __restrict__ bias, int N) {
    __shared__ float sroot[32 * 32];
    __shared__ float sb[32];
    int tid = threadIdx.x;
    for (int i = tid; i < 1024; i += 256) sroot[i] = root[i];
    if (tid < 32) sb[tid] = bias[tid];
    __syncthreads();

    int lane = tid & 31, w = tid >> 5;
    int n = blockIdx.x * 8 + w;
    if (n >= N) return;
    const float* __restrict__ hin = (selIn == 0) ? g_h0 : (selIn == 1) ? g_ha : g_hb;
    float* __restrict__ hout = (selOut == 1) ? g_ha : g_hb;

    float hv = hin[(size_t)n * 32 + lane];
    float acc = sb[lane] + g_agg[(size_t)n * 32 + lane];
    g_agg[(size_t)n * 32 + lane] = 0.0f;
#pragma unroll
    for (int k = 0; k < 32; k++)
        acc += __shfl_sync(0xffffffffu, hv, k) * sroot[k * 32 + lane];
    hout[(size_t)n * 32 + lane] = acc;
}

__global__ void k_zero(float* o, int n) {
    int i = blockIdx.x * blockDim.x + threadIdx.x;
    if (i < n) o[i] = 0.0f;
}

// ---------------------------------------------------------------------------
// readout: out = sum_n sigmoid(relu([h,h0]@Wi0+bi0)@Wi1+bi1) *
//                       (relu(h@Wj0+bj0)@Wj1+bj1)
// ---------------------------------------------------------------------------
__global__ __launch_bounds__(256) void k_readout(
    const float* __restrict__ Wi0, const float* __restrict__ bi0,
    const float* __restrict__ Wi1, const float* __restrict__ bi1,
    const float* __restrict__ Wj0, const float* __restrict__ bj0,
    const float* __restrict__ Wj1, const float* __restrict__ bj1,
    float* __restrict__ out, int N) {
    __shared__ float sW[64 * 128];
    __shared__ float sv1[128];
    __shared__ float sblock;
    int tid = threadIdx.x, lane = tid & 31, w = tid >> 5;
    int n = blockIdx.x * 8 + w;
    bool active = (n < N);

    for (int i = tid; i < 64 * 128; i += 256) sW[i] = Wi0[i];
    for (int i = tid; i < 128; i += 256) sv1[i] = Wi1[i];
    if (tid == 0) sblock = 0.f;
    __syncthreads();

    float za = 0.f, zb = 0.f;
    if (active) {
        za = g_ha[(size_t)n * 32 + lane];   // final h
        zb = g_h0[(size_t)n * 32 + lane];   // h0
    }

    float a0 = bi0[lane], a1 = bi0[lane + 32], a2 = bi0[lane + 64], a3 = bi0[lane + 96];
#pragma unroll
    for (int k = 0; k < 32; k++) {
        float zk = __shfl_sync(0xffffffffu, za, k);
        a0 += zk * sW[k * 128 + lane];
        a1 += zk * sW[k * 128 + lane + 32];
        a2 += zk * sW[k * 128 + lane + 64];
        a3 += zk * sW[k * 128 + lane + 96];
    }
#pragma unroll
    for (int k = 0; k < 32; k++) {
        float zk = __shfl_sync(0xffffffffu, zb, k);
        a0 += zk * sW[(k + 32) * 128 + lane];
        a1 += zk * sW[(k + 32) * 128 + lane + 32];
        a2 += zk * sW[(k + 32) * 128 + lane + 64];
        a3 += zk * sW[(k + 32) * 128 + lane + 96];
    }
    a0 = fmaxf(a0, 0.f); a1 = fmaxf(a1, 0.f); a2 = fmaxf(a2, 0.f); a3 = fmaxf(a3, 0.f);
    float gp = a0 * sv1[lane] + a1 * sv1[lane + 32] + a2 * sv1[lane + 64] + a3 * sv1[lane + 96];
#pragma unroll
    for (int s = 16; s > 0; s >>= 1) gp += __shfl_xor_sync(0xffffffffu, gp, s);
    float gate = 1.0f / (1.0f + expf(-(gp + bi1[0])));

    __syncthreads();   // done reading Wi0
    for (int i = tid; i < 32 * 128; i += 256) sW[i] = Wj0[i];
    for (int i = tid; i < 128; i += 256) sv1[i] = Wj1[i];
    __syncthreads();

    float b0 = bj0[lane], b1 = bj0[lane + 32], b2 = bj0[lane + 64], b3 = bj0[lane + 96];
#pragma unroll
    for (int k = 0; k < 32; k++) {
        float zk = __shfl_sync(0xffffffffu, za, k);
        b0 += zk * sW[k * 128 + lane];
        b1 += zk * sW[k * 128 + lane + 32];
        b2 += zk * sW[k * 128 + lane + 64];
        b3 += zk * sW[k * 128 + lane + 96];
    }
    b0 = fmaxf(b0, 0.f); b1 = fmaxf(b1, 0.f); b2 = fmaxf(b2, 0.f); b3 = fmaxf(b3, 0.f);
    float vp = b0 * sv1[lane] + b1 * sv1[lane + 32] + b2 * sv1[lane + 64] + b3 * sv1[lane + 96];
#pragma unroll
    for (int s = 16; s > 0; s >>= 1) vp += __shfl_xor_sync(0xffffffffu, vp, s);
    float val = vp + bj1[0];

    if (active && lane == 0) atomicAdd(&sblock, gate * val);
    __syncthreads();
    if (tid == 0) atomicAdd(out, sblock);
}

// ---------------------------------------------------------------------------
extern "C" void kernel_launch(void* const* d_in, const int* in_sizes, int n_in,
                              void* d_out, int out_size) {
    const float* x   = (const float*)d_in[0];
    const int*   ei  = (const int*)d_in[1];
    const float* ea  = (const float*)d_in[2];
    const float* Wm0 = (const float*)d_in[3];  const float* bm0 = (const float*)d_in[4];
    const float* Wm1 = (const float*)d_in[5];  const float* bm1 = (const float*)d_in[6];
    const float* Wm2 = (const float*)d_in[7];  const float* bm2 = (const float*)d_in[8];
    const float* root= (const float*)d_in[9];  const float* bias= (const float*)d_in[10];
    const float* Wi0 = (const float*)d_in[11]; const float* bi0 = (const float*)d_in[12];
    const float* Wi1 = (const float*)d_in[13]; const float* bi1 = (const float*)d_in[14];
    const float* Wj0 = (const float*)d_in[15]; const float* bj0 = (const float*)d_in[16];
    const float* Wj1 = (const float*)d_in[17]; const float* bj1 = (const float*)d_in[18];
    int N = in_sizes[0] / 16;
    int E = in_sizes[2] / 16;
    float* out = (float*)d_out;

    k_init<<<(N * 32 + 255) / 256, 256>>>(x, N);
    k_convB<<<(64 * 1024 + 255) / 256, 256>>>(Wm2);
    k_edge_mlp<<<(E + 127) / 128, 128>>>(ea, Wm0, bm0, Wm1, bm1, E);

    dim3 gg((E + 127) / 128, 2);
    k_wgemm<<<gg, 256>>>(bm2, E);

    int msgBlocks = (E + 7) / 8;
    int nodeBlocks = (N + 7) / 8;
    // iter 1: h0 -> ha
    k_msg<<<msgBlocks, 256>>>(ei, 0, E);
    k_update<<<nodeBlocks, 256>>>(0, 1, root, bias, N);
    // iter 2: ha -> hb
    k_msg<<<msgBlocks, 256>>>(ei, 1, E);
    k_update<<<nodeBlocks, 256>>>(1, 2, root, bias, N);
    // iter 3: hb -> ha
    k_msg<<<msgBlocks, 256>>>(ei, 2, E);
    k_update<<<nodeBlocks, 256>>>(2, 1, root, bias, N);

    k_zero<<<1, 32>>>(out, out_size);
    k_readout<<<nodeBlocks, 256>>>(Wi0, bi0, Wi1, bi1, Wj0, bj0, Wj1, bj1, out, N);
}

// round 11
// speedup vs baseline: 1.5171x; 1.1555x over previous
#include <cuda_runtime.h>
#include <cuda_fp16.h>
#include <math.h>
#include <stdint.h>

#define MAXE 400000
#define MAXN 50000

// Scratch (device globals: the sanctioned alloc-free workaround)
__device__ __half g_e2h[(size_t)MAXE * 64];    // 51 MB: edge MLP output (fp16)
__device__ __half g_Bt[64 * 1024];             // Wm2 transposed [n][k], fp16
__device__ __half g_B0t[64 * 16];              // Wm0 transposed [n][k], fp16
__device__ __half g_B1t[64 * 64];              // Wm1 transposed [n][k], fp16
__device__ __half g_Wh[(size_t)MAXE * 1024];   // 819 MB: per-edge W (PERMUTED layout)
__device__ float  g_h0[(size_t)MAXN * 32];
__device__ float  g_ha[(size_t)MAXN * 32];
__device__ float  g_hb[(size_t)MAXN * 32];
__device__ float  g_agg[(size_t)MAXN * 32];

// Permuted W layout: W'[e][h*32 + c*8 + nt*2 + b] = W_e[h][nt*8 + 2c + b]

// ---------------------------------------------------------------------------
__global__ void k_init(const float* __restrict__ x, int N) {
    int i = blockIdx.x * blockDim.x + threadIdx.x;
    if (i < N * 32) {
        int n = i >> 5, o = i & 31;
        g_h0[i] = (o < 16) ? x[n * 16 + o] : 0.0f;
        g_agg[i] = 0.0f;
    }
}

// convB: g_Bt[n][k] = fp16(Wm2[k][n]); also Wm0/Wm1 transposes
__global__ void k_convB(const float* __restrict__ B,
                        const float* __restrict__ W0, const float* __restrict__ W1) {
    int i = blockIdx.x * blockDim.x + threadIdx.x;
    if (i < 64 * 1024) {
        int n = i >> 6, k = i & 63;
        g_Bt[i] = __float2half_rn(B[k * 1024 + n]);
    }
    if (i < 64 * 16) {
        int n = i >> 4, k = i & 15;
        g_B0t[i] = __float2half_rn(W0[k * 64 + n]);
    }
    if (i < 64 * 64) {
        int n = i >> 6, k = i & 63;
        g_B1t[i] = __float2half_rn(W1[k * 64 + n]);
    }
}

// ---------------------------------------------------------------------------
// edge MLP (fp16 tensor cores): e2 = relu(relu(ea@Wm0+bm0)@Wm1+bm1)
// block = 128 edges, 8 warps (4M x 2N), two mma rounds through smem
// ---------------------------------------------------------------------------
#define EP 24    // sEA/sB0 pitch (halves)
#define HP 72    // sH1/sB1 pitch (halves)

__global__ __launch_bounds__(256) void k_edge_mlp(
    const float* __restrict__ ea,
    const float* __restrict__ bm0, const float* __restrict__ bm1, int E) {
    __shared__ __half sEA[128 * EP];   // edge features [row][k<16]
    __shared__ __half sB0[64 * EP];    // Wm0^T [n][k<16]
    __shared__ __half sB1[64 * HP];    // Wm1^T [n][k<64]
    __shared__ __half sH1[128 * HP];   // h1; reused as e2 stage
    __shared__ float  sb0[64], sb1[64];

    int tid = threadIdx.x;
    int bm = blockIdx.x * 128;

    if (tid < 64) sb0[tid] = bm0[tid];
    else if (tid < 128) sb1[tid - 64] = bm1[tid - 64];

    // stage sEA: thread t -> edge t/2, feature-half t&1 (8 fp32 -> 8 fp16)
    {
        int el = tid >> 1, p = tid & 1;
        int rr = bm + el; if (rr >= E) rr = E - 1;
        const float4* src = (const float4*)(ea + (size_t)rr * 16 + p * 8);
        float4 v0 = src[0], v1 = src[1];
        __half2 h0 = __floats2half2_rn(v0.x, v0.y);
        __half2 h1_ = __floats2half2_rn(v0.z, v0.w);
        __half2 h2 = __floats2half2_rn(v1.x, v1.y);
        __half2 h3 = __floats2half2_rn(v1.z, v1.w);
        uint4 pk;
        pk.x = *(unsigned*)&h0; pk.y = *(unsigned*)&h1_;
        pk.z = *(unsigned*)&h2; pk.w = *(unsigned*)&h3;
        *(uint4*)&sEA[el * EP + p * 8] = pk;
    }
    // stage sB0: 64 rows x 16 halves (threads 0..127)
    if (tid < 128) {
        int row = tid >> 1, x = tid & 1;
        uint4 v = *(const uint4*)(g_B0t + row * 16 + x * 8);
        *(uint4*)&sB0[row * EP + x * 8] = v;
    }
    // stage sB1: 64 rows x 64 halves
    {
        int r2 = tid >> 3, x = tid & 7;
#pragma unroll
        for (int i = 0; i < 2; i++) {
            int row = r2 + i * 32;
            uint4 v = *(const uint4*)(g_B1t + (size_t)row * 64 + x * 8);
            *(uint4*)&sB1[row * HP + x * 8] = v;
        }
    }
    __syncthreads();

    int lane = tid & 31;
    int warp = tid >> 5;
    int wm = warp & 3;
    int wn = warp >> 2;
    int g = lane >> 2;
    int c = lane & 3;

    // ---- layer 1: [128,16] @ [16,64] (single mma step, K=16) ----
    float acc[2][4][4];
#pragma unroll
    for (int mt = 0; mt < 2; mt++)
#pragma unroll
        for (int nt = 0; nt < 4; nt++)
#pragma unroll
            for (int q = 0; q < 4; q++) acc[mt][nt][q] = 0.f;
    {
        unsigned a_[2][4];
#pragma unroll
        for (int mt = 0; mt < 2; mt++) {
            int r0 = wm * 32 + mt * 16 + g;
            a_[mt][0] = *(const unsigned*)&sEA[r0 * EP + 2 * c];
            a_[mt][1] = *(const unsigned*)&sEA[(r0 + 8) * EP + 2 * c];
            a_[mt][2] = *(const unsigned*)&sEA[r0 * EP + 2 * c + 8];
            a_[mt][3] = *(const unsigned*)&sEA[(r0 + 8) * EP + 2 * c + 8];
        }
#pragma unroll
        for (int nt = 0; nt < 4; nt++) {
            int n0 = wn * 32 + nt * 8 + g;
            unsigned b0 = *(const unsigned*)&sB0[n0 * EP + 2 * c];
            unsigned b1 = *(const unsigned*)&sB0[n0 * EP + 2 * c + 8];
#pragma unroll
            for (int mt = 0; mt < 2; mt++) {
                asm volatile(
                    "mma.sync.aligned.m16n8k16.row.col.f32.f16.f16.f32 "
                    "{%0,%1,%2,%3}, {%4,%5,%6,%7}, {%8,%9}, {%0,%1,%2,%3};"
                    : "+f"(acc[mt][nt][0]), "+f"(acc[mt][nt][1]),
                      "+f"(acc[mt][nt][2]), "+f"(acc[mt][nt][3])
                    : "r"(a_[mt][0]), "r"(a_[mt][1]), "r"(a_[mt][2]), "r"(a_[mt][3]),
                      "r"(b0), "r"(b1));
            }
        }
    }
    // epilogue: bias + relu -> sH1
#pragma unroll
    for (int nt = 0; nt < 4; nt++) {
        int col = wn * 32 + nt * 8 + 2 * c;
        float bx = sb0[col], by = sb0[col + 1];
#pragma unroll
        for (int mt = 0; mt < 2; mt++) {
            int r0 = wm * 32 + mt * 16 + g;
            __half2 v0 = __floats2half2_rn(fmaxf(acc[mt][nt][0] + bx, 0.f),
                                           fmaxf(acc[mt][nt][1] + by, 0.f));
            *(__half2*)&sH1[r0 * HP + col] = v0;
            __half2 v1 = __floats2half2_rn(fmaxf(acc[mt][nt][2] + bx, 0.f),
                                           fmaxf(acc[mt][nt][3] + by, 0.f));
            *(__half2*)&sH1[(r0 + 8) * HP + col] = v1;
        }
    }
    __syncthreads();

    // ---- layer 2: [128,64] @ [64,64] (K=64, 4 steps) ----
#pragma unroll
    for (int mt = 0; mt < 2; mt++)
#pragma unroll
        for (int nt = 0; nt < 4; nt++)
#pragma unroll
            for (int q = 0; q < 4; q++) acc[mt][nt][q] = 0.f;

#pragma unroll
    for (int kk = 0; kk < 4; kk++) {
        int kb = kk * 16;
        unsigned a_[2][4];
#pragma unroll
        for (int mt = 0; mt < 2; mt++) {
            int r0 = wm * 32 + mt * 16 + g;
            a_[mt][0] = *(const unsigned*)&sH1[r0 * HP + kb + 2 * c];
            a_[mt][1] = *(const unsigned*)&sH1[(r0 + 8) * HP + kb + 2 * c];
            a_[mt][2] = *(const unsigned*)&sH1[r0 * HP + kb + 2 * c + 8];
            a_[mt][3] = *(const unsigned*)&sH1[(r0 + 8) * HP + kb + 2 * c + 8];
        }
#pragma unroll
        for (int nt = 0; nt < 4; nt++) {
            int n0 = wn * 32 + nt * 8 + g;
            unsigned b0 = *(const unsigned*)&sB1[n0 * HP + kb + 2 * c];
            unsigned b1 = *(const unsigned*)&sB1[n0 * HP + kb + 2 * c + 8];
#pragma unroll
            for (int mt = 0; mt < 2; mt++) {
                asm volatile(
                    "mma.sync.aligned.m16n8k16.row.col.f32.f16.f16.f32 "
                    "{%0,%1,%2,%3}, {%4,%5,%6,%7}, {%8,%9}, {%0,%1,%2,%3};"
                    : "+f"(acc[mt][nt][0]), "+f"(acc[mt][nt][1]),
                      "+f"(acc[mt][nt][2]), "+f"(acc[mt][nt][3])
                    : "r"(a_[mt][0]), "r"(a_[mt][1]), "r"(a_[mt][2]), "r"(a_[mt][3]),
                      "r"(b0), "r"(b1));
            }
        }
    }
    __syncthreads();   // all sH1 reads done before reuse

    // epilogue: bias + relu -> sH1 (reused as e2 stage)
#pragma unroll
    for (int nt = 0; nt < 4; nt++) {
        int col = wn * 32 + nt * 8 + 2 * c;
        float bx = sb1[col], by = sb1[col + 1];
#pragma unroll
        for (int mt = 0; mt < 2; mt++) {
            int r0 = wm * 32 + mt * 16 + g;
            __half2 v0 = __floats2half2_rn(fmaxf(acc[mt][nt][0] + bx, 0.f),
                                           fmaxf(acc[mt][nt][1] + by, 0.f));
            *(__half2*)&sH1[r0 * HP + col] = v0;
            __half2 v1 = __floats2half2_rn(fmaxf(acc[mt][nt][2] + bx, 0.f),
                                           fmaxf(acc[mt][nt][3] + by, 0.f));
            *(__half2*)&sH1[(r0 + 8) * HP + col] = v1;
        }
    }
    __syncthreads();

    // coalesced e2 store: 128 rows x 64 halves
    {
        int r = tid >> 3, x = tid & 7;
#pragma unroll
        for (int i = 0; i < 4; i++) {
            int row = r + i * 32;
            int rr = bm + row;
            if (rr < E) {
                uint4 v = *(const uint4*)&sH1[row * HP + x * 8];
                *(uint4*)(g_e2h + (size_t)rr * 64 + x * 8) = v;
            }
        }
    }
}

// ---------------------------------------------------------------------------
// W GEMM (fp16 tensor cores): permuted-layout W (unchanged from R10)
// ---------------------------------------------------------------------------
#define HPITCH 72

__global__ __launch_bounds__(256) void k_wgemm(
    const float* __restrict__ bias, int E) {
    __shared__ __half sA[128 * HPITCH];
    __shared__ __half sB[64 * HPITCH];
    __shared__ float  sbias[64];

    int bm = blockIdx.x * 128;
    int bn0 = blockIdx.y * 512;
    int tid = threadIdx.x;
    int r = tid >> 3;
    int x = tid & 7;

#pragma unroll
    for (int i = 0; i < 4; i++) {
        int row = r + i * 32;
        int rr = bm + row; if (rr >= E) rr = E - 1;
        uint4 va = *(const uint4*)(g_e2h + (size_t)rr * 64 + x * 8);
        *(uint4*)((char*)sA + row * 144 + x * 16) = va;
    }

    int lane = tid & 31;
    int warp = tid >> 5;
    int wm = warp & 3;
    int wn = warp >> 2;
    int g = lane >> 2;
    int c = lane & 3;

#pragma unroll 1
    for (int ch = 0; ch < 8; ch++) {
        int bn = bn0 + ch * 64;

#pragma unroll
        for (int i = 0; i < 2; i++) {
            int row = r + i * 32;
            uint4 vb = *(const uint4*)(g_Bt + (size_t)(bn + row) * 64 + x * 8);
            *(uint4*)((char*)sB + row * 144 + x * 16) = vb;
        }
        if (tid < 64) sbias[tid] = bias[bn + tid];
        __syncthreads();

        float acc[2][4][4];
#pragma unroll
        for (int mt = 0; mt < 2; mt++)
#pragma unroll
            for (int nt = 0; nt < 4; nt++)
#pragma unroll
                for (int q = 0; q < 4; q++) acc[mt][nt][q] = 0.f;

#pragma unroll
        for (int kk = 0; kk < 4; kk++) {
            int kb = kk * 16;
            unsigned a_[2][4];
#pragma unroll
            for (int mt = 0; mt < 2; mt++) {
                int r0 = wm * 32 + mt * 16 + g;
                a_[mt][0] = *(const unsigned*)&sA[r0 * HPITCH + kb + 2 * c];
                a_[mt][1] = *(const unsigned*)&sA[(r0 + 8) * HPITCH + kb + 2 * c];
                a_[mt][2] = *(const unsigned*)&sA[r0 * HPITCH + kb + 2 * c + 8];
                a_[mt][3] = *(const unsigned*)&sA[(r0 + 8) * HPITCH + kb + 2 * c + 8];
            }
            unsigned b_[4][2];
#pragma unroll
            for (int nt = 0; nt < 4; nt++) {
                int n0 = wn * 32 + nt * 8 + g;
                b_[nt][0] = *(const unsigned*)&sB[n0 * HPITCH + kb + 2 * c];
                b_[nt][1] = *(const unsigned*)&sB[n0 * HPITCH + kb + 2 * c + 8];
            }
#pragma unroll
            for (int mt = 0; mt < 2; mt++)
#pragma unroll
                for (int nt = 0; nt < 4; nt++) {
                    asm volatile(
                        "mma.sync.aligned.m16n8k16.row.col.f32.f16.f16.f32 "
                        "{%0,%1,%2,%3}, {%4,%5,%6,%7}, {%8,%9}, {%0,%1,%2,%3};"
                        : "+f"(acc[mt][nt][0]), "+f"(acc[mt][nt][1]),
                          "+f"(acc[mt][nt][2]), "+f"(acc[mt][nt][3])
                        : "r"(a_[mt][0]), "r"(a_[mt][1]), "r"(a_[mt][2]), "r"(a_[mt][3]),
                          "r"(b_[nt][0]), "r"(b_[nt][1]));
                }
        }

        {
            int hcol = (bn + wn * 32);
            float bb[4][2];
#pragma unroll
            for (int nt = 0; nt < 4; nt++) {
                int col = wn * 32 + nt * 8 + 2 * c;
                bb[nt][0] = sbias[col];
                bb[nt][1] = sbias[col + 1];
            }
#pragma unroll
            for (int mt = 0; mt < 2; mt++) {
#pragma unroll
                for (int q = 0; q < 2; q++) {
                    int er = bm + wm * 32 + mt * 16 + q * 8 + g;
                    if (er < E) {
                        __half2 v[4];
#pragma unroll
                        for (int nt = 0; nt < 4; nt++)
                            v[nt] = __floats2half2_rn(acc[mt][nt][2 * q] + bb[nt][0],
                                                      acc[mt][nt][2 * q + 1] + bb[nt][1]);
                        uint4 pk;
                        pk.x = *(unsigned*)&v[0]; pk.y = *(unsigned*)&v[1];
                        pk.z = *(unsigned*)&v[2]; pk.w = *(unsigned*)&v[3];
                        *(uint4*)(g_Wh + (size_t)er * 1024 + hcol + c * 8) = pk;
                    }
                }
            }
        }
        __syncthreads();
    }
}

// ---------------------------------------------------------------------------
// message passing (unchanged from R10)
// ---------------------------------------------------------------------------
__global__ __launch_bounds__(256) void k_msg(const int* __restrict__ ei, int selIn, int E) {
    int gw = (blockIdx.x * blockDim.x + threadIdx.x) >> 5;
    int lane = threadIdx.x & 31;
    if (gw >= E) return;
    const float* __restrict__ h = (selIn == 0) ? g_h0 : (selIn == 1) ? g_ha : g_hb;

    int2 sd = ((const int2*)ei)[gw];
    int src = sd.x, dst = sd.y;
    float hval = h[(size_t)src * 32 + lane];

    const uint4* __restrict__ W16 = (const uint4*)(g_Wh + (size_t)gw * 1024);
    float acc[8];
#pragma unroll
    for (int j = 0; j < 8; j++) acc[j] = 0.f;

#pragma unroll
    for (int i = 0; i < 4; i++) {
        uint4 w = W16[lane + 32 * i];
        float hs = __shfl_sync(0xffffffffu, hval, (lane >> 2) + 8 * i);
        const __half2* h2 = (const __half2*)&w;
#pragma unroll
        for (int j = 0; j < 4; j++) {
            float2 f = __half22float2(h2[j]);
            acc[2 * j]     += hs * f.x;
            acc[2 * j + 1] += hs * f.y;
        }
    }
#pragma unroll
    for (int m = 4; m <= 16; m <<= 1) {
#pragma unroll
        for (int j = 0; j < 8; j++)
            acc[j] += __shfl_xor_sync(0xffffffffu, acc[j], m);
    }
    int k = lane >> 2;
    float v = acc[0];
    if (k == 1) v = acc[1];
    if (k == 2) v = acc[2];
    if (k == 3) v = acc[3];
    if (k == 4) v = acc[4];
    if (k == 5) v = acc[5];
    if (k == 6) v = acc[6];
    if (k == 7) v = acc[7];
    int o = ((k >> 1) << 3) + ((lane & 3) << 1) + (k & 1);
    atomicAdd(&g_agg[(size_t)dst * 32 + o], v);
}

// ---------------------------------------------------------------------------
// node update (widened: 1024 threads, 32 nodes per block)
// ---------------------------------------------------------------------------
__global__ __launch_bounds__(1024) void k_update(
    int selIn, int selOut, const float* __restrict__ root,
    const float* __restrict__ bias, int N) {
    __shared__ float sroot[32 * 32];
    __shared__ float sb[32];
    int tid = threadIdx.x;
    if (tid < 1024) sroot[tid] = root[tid];
    if (tid < 32) sb[tid] = bias[tid];
    __syncthreads();

    int lane = tid & 31, w = tid >> 5;
    int n = blockIdx.x * 32 + w;
    if (n >= N) return;
    const float* __restrict__ hin = (selIn == 0) ? g_h0 : (selIn == 1) ? g_ha : g_hb;
    float* __restrict__ hout = (selOut == 1) ? g_ha : g_hb;

    float hv = hin[(size_t)n * 32 + lane];
    float acc = sb[lane] + g_agg[(size_t)n * 32 + lane];
    g_agg[(size_t)n * 32 + lane] = 0.0f;
#pragma unroll
    for (int k = 0; k < 32; k++)
        acc += __shfl_sync(0xffffffffu, hv, k) * sroot[k * 32 + lane];
    hout[(size_t)n * 32 + lane] = acc;
}

__global__ void k_zero(float* o, int n) {
    int i = blockIdx.x * blockDim.x + threadIdx.x;
    if (i < n) o[i] = 0.0f;
}

// ---------------------------------------------------------------------------
// readout (widened: 1024 threads, 32 nodes per block)
// ---------------------------------------------------------------------------
__global__ __launch_bounds__(1024) void k_readout(
    const float* __restrict__ Wi0, const float* __restrict__ bi0,
    const float* __restrict__ Wi1, const float* __restrict__ bi1,
    const float* __restrict__ Wj0, const float* __restrict__ bj0,
    const float* __restrict__ Wj1, const float* __restrict__ bj1,
    float* __restrict__ out, int N) {
    __shared__ float sW[64 * 128];
    __shared__ float sv1[128];
    __shared__ float sblock;
    int tid = threadIdx.x, lane = tid & 31, w = tid >> 5;
    int n = blockIdx.x * 32 + w;
    bool active = (n < N);

    for (int i = tid; i < 64 * 128; i += 1024) sW[i] = Wi0[i];
    if (tid < 128) sv1[tid] = Wi1[tid];
    if (tid == 0) sblock = 0.f;
    __syncthreads();

    float za = 0.f, zb = 0.f;
    if (active) {
        za = g_ha[(size_t)n * 32 + lane];
        zb = g_h0[(size_t)n * 32 + lane];
    }

    float a0 = bi0[lane], a1 = bi0[lane + 32], a2 = bi0[lane + 64], a3 = bi0[lane + 96];
#pragma unroll
    for (int k = 0; k < 32; k++) {
        float zk = __shfl_sync(0xffffffffu, za, k);
        a0 += zk * sW[k * 128 + lane];
        a1 += zk * sW[k * 128 + lane + 32];
        a2 += zk * sW[k * 128 + lane + 64];
        a3 += zk * sW[k * 128 + lane + 96];
    }
#pragma unroll
    for (int k = 0; k < 32; k++) {
        float zk = __shfl_sync(0xffffffffu, zb, k);
        a0 += zk * sW[(k + 32) * 128 + lane];
        a1 += zk * sW[(k + 32) * 128 + lane + 32];
        a2 += zk * sW[(k + 32) * 128 + lane + 64];
        a3 += zk * sW[(k + 32) * 128 + lane + 96];
    }
    a0 = fmaxf(a0, 0.f); a1 = fmaxf(a1, 0.f); a2 = fmaxf(a2, 0.f); a3 = fmaxf(a3, 0.f);
    float gp = a0 * sv1[lane] + a1 * sv1[lane + 32] + a2 * sv1[lane + 64] + a3 * sv1[lane + 96];
#pragma unroll
    for (int s = 16; s > 0; s >>= 1) gp += __shfl_xor_sync(0xffffffffu, gp, s);
    float gate = 1.0f / (1.0f + expf(-(gp + bi1[0])));

    __syncthreads();
    for (int i = tid; i < 32 * 128; i += 1024) sW[i] = Wj0[i];
    if (tid < 128) sv1[tid] = Wj1[tid];
    __syncthreads();

    float b0 = bj0[lane], b1 = bj0[lane + 32], b2 = bj0[lane + 64], b3 = bj0[lane + 96];
#pragma unroll
    for (int k = 0; k < 32; k++) {
        float zk = __shfl_sync(0xffffffffu, za, k);
        b0 += zk * sW[k * 128 + lane];
        b1 += zk * sW[k * 128 + lane + 32];
        b2 += zk * sW[k * 128 + lane + 64];
        b3 += zk * sW[k * 128 + lane + 96];
    }
    b0 = fmaxf(b0, 0.f); b1 = fmaxf(b1, 0.f); b2 = fmaxf(b2, 0.f); b3 = fmaxf(b3, 0.f);
    float vp = b0 * sv1[lane] + b1 * sv1[lane + 32] + b2 * sv1[lane + 64] + b3 * sv1[lane + 96];
#pragma unroll
    for (int s = 16; s > 0; s >>= 1) vp += __shfl_xor_sync(0xffffffffu, vp, s);
    float val = vp + bj1[0];

    if (active && lane == 0) atomicAdd(&sblock, gate * val);
    __syncthreads();
    if (tid == 0) atomicAdd(out, sblock);
}

// ---------------------------------------------------------------------------
extern "C" void kernel_launch(void* const* d_in, const int* in_sizes, int n_in,
                              void* d_out, int out_size) {
    const float* x   = (const float*)d_in[0];
    const int*   ei  = (const int*)d_in[1];
    const float* ea  = (const float*)d_in[2];
    const float* Wm0 = (const float*)d_in[3];  const float* bm0 = (const float*)d_in[4];
    const float* Wm1 = (const float*)d_in[5];  const float* bm1 = (const float*)d_in[6];
    const float* Wm2 = (const float*)d_in[7];  const float* bm2 = (const float*)d_in[8];
    const float* root= (const float*)d_in[9];  const float* bias= (const float*)d_in[10];
    const float* Wi0 = (const float*)d_in[11]; const float* bi0 = (const float*)d_in[12];
    const float* Wi1 = (const float*)d_in[13]; const float* bi1 = (const float*)d_in[14];
    const float* Wj0 = (const float*)d_in[15]; const float* bj0 = (const float*)d_in[16];
    const float* Wj1 = (const float*)d_in[17]; const float* bj1 = (const float*)d_in[18];
    int N = in_sizes[0] / 16;
    int E = in_sizes[2] / 16;
    float* out = (float*)d_out;

    k_init<<<(N * 32 + 255) / 256, 256>>>(x, N);
    k_convB<<<(64 * 1024 + 255) / 256, 256>>>(Wm2, Wm0, Wm1);
    k_edge_mlp<<<(E + 127) / 128, 256>>>(ea, bm0, bm1, E);

    dim3 gg((E + 127) / 128, 2);
    k_wgemm<<<gg, 256>>>(bm2, E);

    int msgBlocks = (E + 7) / 8;
    int nodeBlocks = (N + 31) / 32;
    // iter 1: h0 -> ha
    k_msg<<<msgBlocks, 256>>>(ei, 0, E);
    k_update<<<nodeBlocks, 1024>>>(0, 1, root, bias, N);
    // iter 2: ha -> hb
    k_msg<<<msgBlocks, 256>>>(ei, 1, E);
    k_update<<<nodeBlocks, 1024>>>(1, 2, root, bias, N);
    // iter 3: hb -> ha
    k_msg<<<msgBlocks, 256>>>(ei, 2, E);
    k_update<<<nodeBlocks, 1024>>>(2, 1, root, bias, N);

    k_zero<<<1, 32>>>(out, out_size);
    k_readout<<<nodeBlocks, 1024>>>(Wi0, bi0, Wi1, bi1, Wj0, bj0, Wj1, bj1, out, N);
}